// round 5
// baseline (speedup 1.0000x reference)
#include <cuda_runtime.h>
#include <cuda_bf16.h>
#include <math.h>
#include <stdint.h>

#define B_SZ    2
#define T_SEQ   2048
#define D_MODEL 2048
#define N_HEADS 16
#define N_KV    4
#define HD      128
#define KDIM    2048
#define MROWS   (B_SZ * T_SEQ)          // 4096

// ---------------- scratch (static device globals; no allocs) ----------------
__device__ float g_q[(size_t)B_SZ * N_HEADS * T_SEQ * HD];
__device__ float g_k[(size_t)B_SZ * N_KV   * T_SEQ * HD];
__device__ float g_v[(size_t)B_SZ * N_KV   * T_SEQ * HD];

__device__ __nv_bfloat16 g_xh[(size_t)MROWS * KDIM];
__device__ __nv_bfloat16 g_xl[(size_t)MROWS * KDIM];
__device__ __nv_bfloat16 g_wh[(size_t)3072 * KDIM];   // wq|wk|wv stacked
__device__ __nv_bfloat16 g_wl[(size_t)3072 * KDIM];
__device__ __nv_bfloat16 g_woh[(size_t)2048 * KDIM];
__device__ __nv_bfloat16 g_wol[(size_t)2048 * KDIM];
__device__ __nv_bfloat16 g_ah[(size_t)MROWS * KDIM];  // attention out hi/lo
__device__ __nv_bfloat16 g_al[(size_t)MROWS * KDIM];

__device__ __nv_bfloat16 g_qh[(size_t)B_SZ * N_HEADS * T_SEQ * HD];
__device__ __nv_bfloat16 g_ql[(size_t)B_SZ * N_HEADS * T_SEQ * HD];
__device__ __nv_bfloat16 g_kh[(size_t)B_SZ * N_KV * T_SEQ * HD];
__device__ __nv_bfloat16 g_kl[(size_t)B_SZ * N_KV * T_SEQ * HD];
__device__ __nv_bfloat16 g_vh[(size_t)B_SZ * N_KV * T_SEQ * HD];
__device__ __nv_bfloat16 g_vl[(size_t)B_SZ * N_KV * T_SEQ * HD];

// ---------------- helpers ----------------
__device__ __forceinline__ uint32_t smem_to_u32(const void* p) {
    uint32_t a;
    asm("{ .reg .u64 t; cvta.to.shared.u64 t, %1; cvt.u32.u64 %0, t; }" : "=r"(a) : "l"(p));
    return a;
}
#define SW128(off) ((off) ^ (((off) >> 3) & 0x70))

__device__ __forceinline__ void cp16(uint32_t saddr, const void* g) {
    asm volatile("cp.async.cg.shared.global [%0], [%1], 16;\n" :: "r"(saddr), "l"(g));
}
#define LDSM_X4(r, a) \
    asm volatile("ldmatrix.sync.aligned.m8n8.x4.shared.b16 {%0,%1,%2,%3}, [%4];" \
        : "=r"((r)[0]), "=r"((r)[1]), "=r"((r)[2]), "=r"((r)[3]) : "r"(a))
#define LDSM_X4_T(r, a) \
    asm volatile("ldmatrix.sync.aligned.m8n8.x4.trans.shared.b16 {%0,%1,%2,%3}, [%4];" \
        : "=r"((r)[0]), "=r"((r)[1]), "=r"((r)[2]), "=r"((r)[3]) : "r"(a))
#define MMA16816(c, a, b0, b1) \
    asm volatile("mma.sync.aligned.m16n8k16.row.col.f32.bf16.bf16.f32 " \
        "{%0,%1,%2,%3}, {%4,%5,%6,%7}, {%8,%9}, {%0,%1,%2,%3};" \
        : "+f"((c)[0]), "+f"((c)[1]), "+f"((c)[2]), "+f"((c)[3]) \
        : "r"((a)[0]), "r"((a)[1]), "r"((a)[2]), "r"((a)[3]), "r"(b0), "r"(b1))

__device__ __forceinline__ uint32_t packbf(float a, float b) {
    __nv_bfloat162 t = __floats2bfloat162_rn(a, b);
    return reinterpret_cast<uint32_t&>(t);
}

// ---------------- fp32 -> bf16 hi/lo split ----------------
__global__ void convert_hilo(const float* __restrict__ src,
                             __nv_bfloat16* __restrict__ hi,
                             __nv_bfloat16* __restrict__ lo, int n4)
{
    int i = blockIdx.x * blockDim.x + threadIdx.x;
    if (i >= n4) return;
    float4 v = ((const float4*)src)[i];
    __nv_bfloat16 h0 = __float2bfloat16(v.x), h1 = __float2bfloat16(v.y);
    __nv_bfloat16 h2 = __float2bfloat16(v.z), h3 = __float2bfloat16(v.w);
    __nv_bfloat16 l0 = __float2bfloat16(v.x - __bfloat162float(h0));
    __nv_bfloat16 l1 = __float2bfloat16(v.y - __bfloat162float(h1));
    __nv_bfloat16 l2 = __float2bfloat16(v.z - __bfloat162float(h2));
    __nv_bfloat16 l3 = __float2bfloat16(v.w - __bfloat162float(h3));
    ((__nv_bfloat162*)hi)[2 * i]     = __nv_bfloat162(h0, h1);
    ((__nv_bfloat162*)hi)[2 * i + 1] = __nv_bfloat162(h2, h3);
    ((__nv_bfloat162*)lo)[2 * i]     = __nv_bfloat162(l0, l1);
    ((__nv_bfloat162*)lo)[2 * i + 1] = __nv_bfloat162(l2, l3);
}

// ---------------- mma.sync split-bf16 GEMM: C[M,N] = A @ B^T ----------------
// 3-stage cp.async ring, one barrier per 64-K chunk.
#define OFF_AH 0
#define OFF_AL 16384
#define OFF_BH 32768
#define OFF_BL 49152
#define STAGE_BYTES 65536
#define GEMM_SMEM (3 * STAGE_BYTES)     // 196608

template<int MODE>
__global__ __launch_bounds__(256, 1)
void gemm_mma(const __nv_bfloat16* __restrict__ Ah, const __nv_bfloat16* __restrict__ Al,
              const __nv_bfloat16* __restrict__ Bh, const __nv_bfloat16* __restrict__ Bl,
              float* __restrict__ C)
{
    extern __shared__ __align__(1024) char smem[];
    const uint32_t sb = smem_to_u32(smem);
    const int tid  = threadIdx.x;
    const int wid  = tid >> 5;
    const int lane = tid & 31;
    const int warp_m = (wid & 3) * 32;
    const int warp_n = (wid >> 2) * 64;
    const int bm0 = blockIdx.y * 128;
    const int bn0 = blockIdx.x * 128;

    float acc[2][8][4];
    #pragma unroll
    for (int mt = 0; mt < 2; mt++)
        #pragma unroll
        for (int nt = 0; nt < 8; nt++)
            #pragma unroll
            for (int i = 0; i < 4; i++) acc[mt][nt][i] = 0.f;

    auto load_chunk = [&](int c) {
        uint32_t st = sb + (uint32_t)(c % 3) * STAGE_BYTES;
        int k0 = c * 64;
        #pragma unroll
        for (int j = 0; j < 4; j++) {
            int i = tid + j * 256;
            int row = i >> 3, cb = (i & 7) * 16;
            uint32_t so = SW128((uint32_t)(row * 128 + cb));
            size_t goA = ((size_t)(bm0 + row) * KDIM + k0) * 2 + cb;
            size_t goB = ((size_t)(bn0 + row) * KDIM + k0) * 2 + cb;
            cp16(st + OFF_AH + so, (const char*)Ah + goA);
            cp16(st + OFF_AL + so, (const char*)Al + goA);
            cp16(st + OFF_BH + so, (const char*)Bh + goB);
            cp16(st + OFF_BL + so, (const char*)Bl + goB);
        }
        asm volatile("cp.async.commit_group;\n");
    };

    load_chunk(0);
    load_chunk(1);

    const int NC = KDIM / 64;
    for (int c = 0; c < NC; c++) {
        if (c == NC - 1) asm volatile("cp.async.wait_group 0;\n");
        else             asm volatile("cp.async.wait_group 1;\n");
        __syncthreads();
        if (c + 2 < NC) load_chunk(c + 2);

        uint32_t st = sb + (uint32_t)(c % 3) * STAGE_BYTES;
        #pragma unroll
        for (int ks = 0; ks < 4; ks++) {
            uint32_t ah[2][4], al[2][4], bh[4][4], bl[4][4];
            int lrow = (lane & 7) + ((lane >> 3) & 1) * 8;
            int lcb  = ks * 32 + (lane >> 4) * 16;
            #pragma unroll
            for (int mt = 0; mt < 2; mt++) {
                int arow = warp_m + mt * 16 + lrow;
                uint32_t ad = st + OFF_AH + SW128((uint32_t)(arow * 128 + lcb));
                LDSM_X4(ah[mt], ad);
                LDSM_X4(al[mt], ad + (OFF_AL - OFF_AH));
            }
            #pragma unroll
            for (int nt = 0; nt < 4; nt++) {
                int brow = warp_n + nt * 16 + lrow;
                uint32_t bd = st + OFF_BH + SW128((uint32_t)(brow * 128 + lcb));
                LDSM_X4(bh[nt], bd);
                LDSM_X4(bl[nt], bd + (OFF_BL - OFF_BH));
            }
            #pragma unroll
            for (int mt = 0; mt < 2; mt++) {
                #pragma unroll
                for (int nt4 = 0; nt4 < 4; nt4++) {
                    MMA16816(acc[mt][2*nt4],   ah[mt], bh[nt4][0], bh[nt4][2]);
                    MMA16816(acc[mt][2*nt4],   ah[mt], bl[nt4][0], bl[nt4][2]);
                    MMA16816(acc[mt][2*nt4],   al[mt], bh[nt4][0], bh[nt4][2]);
                    MMA16816(acc[mt][2*nt4+1], ah[mt], bh[nt4][1], bh[nt4][3]);
                    MMA16816(acc[mt][2*nt4+1], ah[mt], bl[nt4][1], bl[nt4][3]);
                    MMA16816(acc[mt][2*nt4+1], al[mt], bh[nt4][1], bh[nt4][3]);
                }
            }
        }
    }

    const int rbase = bm0 + warp_m + (lane >> 2);
    const int cbase = bn0 + warp_n + (lane & 3) * 2;
    #pragma unroll
    for (int mt = 0; mt < 2; mt++) {
        #pragma unroll
        for (int hh = 0; hh < 2; hh++) {
            int row = rbase + mt * 16 + hh * 8;
            #pragma unroll
            for (int nt = 0; nt < 8; nt++) {
                int col = cbase + nt * 8;
                float2 v = make_float2(acc[mt][nt][2*hh], acc[mt][nt][2*hh+1]);
                if (MODE == 0) {
                    *(float2*)&C[(size_t)row * 2048 + col] = v;
                } else {
                    int b = row >> 11, tq = row & (T_SEQ - 1), d = col & 127;
                    float* base;
                    if (col < 2048) {
                        int h = col >> 7;
                        base = g_q + (((size_t)(b * N_HEADS + h) * T_SEQ + tq) * HD + d);
                    } else if (col < 2560) {
                        int h = (col - 2048) >> 7;
                        base = g_k + (((size_t)(b * N_KV + h) * T_SEQ + tq) * HD + d);
                    } else {
                        int h = (col - 2560) >> 7;
                        base = g_v + (((size_t)(b * N_KV + h) * T_SEQ + tq) * HD + d);
                    }
                    *(float2*)base = v;
                }
            }
        }
    }
}

// ---------------- RoPE: fp32 in -> rotated, scaled bf16 hi/lo out ----------------
__global__ void rope_split(const float* __restrict__ src,
                           __nv_bfloat16* __restrict__ hi,
                           __nv_bfloat16* __restrict__ lo,
                           long total_pairs, float scale)
{
    long idx = (long)blockIdx.x * blockDim.x + threadIdx.x;
    if (idx >= total_pairs) return;
    int  i   = (int)(idx & 63);
    long row = idx >> 6;
    int  tpos = (int)(row & (T_SEQ - 1));
    const float* p = src + row * HD;
    float inv = __expf(-((float)i / 64.0f) * 13.815510557964274f);
    float s, c;
    sincosf((float)tpos * inv, &s, &c);
    float x1 = p[i], x2 = p[i + 64];
    float r1 = (x1 * c - x2 * s) * scale;
    float r2 = (x2 * c + x1 * s) * scale;
    __nv_bfloat16 h1 = __float2bfloat16(r1), h2 = __float2bfloat16(r2);
    hi[row * HD + i]      = h1;
    hi[row * HD + i + 64] = h2;
    lo[row * HD + i]      = __float2bfloat16(r1 - __bfloat162float(h1));
    lo[row * HD + i + 64] = __float2bfloat16(r2 - __bfloat162float(h2));
}

// ---------------- tensor-core flash attention (split-bf16, causal, GQA) ----------
// BM=128 q-rows, 8 warps x 16 rows, BN=64 kv per stage, 3-stage KV ring.
// Q-hi fragments live in registers; Q-lo persistent in smem.
#define ATT_QL    0
#define ATT_ST0   32768
#define ATT_STAGE 65536
#define ATT_KH 0
#define ATT_KL 16384
#define ATT_VH 32768
#define ATT_VL 49152
#define ATT_SMEM (ATT_ST0 + 3 * ATT_STAGE)   // 229376

__device__ __forceinline__ uint32_t swz256(int row, int cb) {
    return (uint32_t)(row * 256 + ((cb ^ (row & 7)) << 4));
}

__global__ __launch_bounds__(256, 1)
void attn_mma(const __nv_bfloat16* __restrict__ qh, const __nv_bfloat16* __restrict__ ql,
              const __nv_bfloat16* __restrict__ kh, const __nv_bfloat16* __restrict__ kl,
              const __nv_bfloat16* __restrict__ vh, const __nv_bfloat16* __restrict__ vl,
              __nv_bfloat16* __restrict__ oh, __nv_bfloat16* __restrict__ ol)
{
    extern __shared__ __align__(1024) char smem[];
    const uint32_t sb = smem_to_u32(smem);
    const int tid  = threadIdx.x;
    const int w    = tid >> 5;
    const int lane = tid & 31;
    const int qt   = (gridDim.x - 1) - blockIdx.x;
    const int bh   = blockIdx.y;
    const int b    = bh >> 4;
    const int h    = bh & 15;
    const int kvh  = h >> 2;

    const size_t qoff = ((size_t)bh * T_SEQ + (size_t)qt * 128) * HD;
    const size_t koff = (size_t)(b * N_KV + kvh) * T_SEQ * HD;

    const int r4 = lane >> 2;
    const int lrow = (lane & 7) + ((lane >> 3) & 1) * 8;

    // ---- preamble: Q-hi (temp, stage0 region) + Q-lo (persistent) ----
    #pragma unroll
    for (int j = 0; j < 8; j++) {
        int i = tid + j * 256;
        int row = i >> 4, cb = i & 15;
        uint32_t so = swz256(row, cb);
        size_t go = (qoff + (size_t)row * HD) * 2 + cb * 16;
        cp16(sb + ATT_ST0 + so, (const char*)qh + go);
        cp16(sb + ATT_QL  + so, (const char*)ql + go);
    }
    asm volatile("cp.async.commit_group;\n");
    asm volatile("cp.async.wait_group 0;\n");
    __syncthreads();

    uint32_t qhf[8][4];
    #pragma unroll
    for (int ks = 0; ks < 8; ks++) {
        int cb = 2 * ks + (lane >> 4);
        LDSM_X4(qhf[ks], sb + ATT_ST0 + swz256(16 * w + lrow, cb));
    }
    __syncthreads();   // everyone done reading temp Q-hi before KV stage 0 overwrites it

    auto load_stage = [&](int kt) {
        uint32_t st = sb + ATT_ST0 + (uint32_t)(kt % 3) * ATT_STAGE;
        size_t base = (koff + (size_t)kt * 64 * HD) * 2;
        #pragma unroll
        for (int j = 0; j < 4; j++) {
            int i = tid + j * 256;
            int row = i >> 4, cb = i & 15;
            uint32_t so = swz256(row, cb);
            size_t go = base + (size_t)row * 256 + cb * 16;
            cp16(st + ATT_KH + so, (const char*)kh + go);
            cp16(st + ATT_KL + so, (const char*)kl + go);
            cp16(st + ATT_VH + so, (const char*)vh + go);
            cp16(st + ATT_VL + so, (const char*)vl + go);
        }
        asm volatile("cp.async.commit_group;\n");
    };

    const int nkt = 2 * (qt + 1);
    load_stage(0);
    load_stage(1);

    float acc[16][4];
    #pragma unroll
    for (int nt = 0; nt < 16; nt++)
        #pragma unroll
        for (int i = 0; i < 4; i++) acc[nt][i] = 0.f;
    float m0 = -1e30f, m1 = -1e30f, l0 = 0.f, l1 = 0.f;

    const int qrow0 = qt * 128 + 16 * w + r4;

    for (int kt = 0; kt < nkt; kt++) {
        if (kt == nkt - 1) asm volatile("cp.async.wait_group 0;\n");
        else               asm volatile("cp.async.wait_group 1;\n");
        __syncthreads();
        if (kt + 2 < nkt) load_stage(kt + 2);
        uint32_t st = sb + ATT_ST0 + (uint32_t)(kt % 3) * ATT_STAGE;

        // ---- S = Q K^T ----
        float sacc[8][4];
        #pragma unroll
        for (int nt = 0; nt < 8; nt++)
            #pragma unroll
            for (int i = 0; i < 4; i++) sacc[nt][i] = 0.f;

        #pragma unroll
        for (int ks = 0; ks < 8; ks++) {
            int cb = 2 * ks + (lane >> 4);
            uint32_t ql4[4];
            LDSM_X4(ql4, sb + ATT_QL + swz256(16 * w + lrow, cb));
            #pragma unroll
            for (int nt2 = 0; nt2 < 4; nt2++) {
                uint32_t bd = st + ATT_KH + swz256(16 * nt2 + lrow, cb);
                uint32_t kh4[4], kl4[4];
                LDSM_X4(kh4, bd);
                LDSM_X4(kl4, bd + (ATT_KL - ATT_KH));
                MMA16816(sacc[2*nt2],   qhf[ks], kh4[0], kh4[2]);
                MMA16816(sacc[2*nt2],   qhf[ks], kl4[0], kl4[2]);
                MMA16816(sacc[2*nt2],   ql4,     kh4[0], kh4[2]);
                MMA16816(sacc[2*nt2+1], qhf[ks], kh4[1], kh4[3]);
                MMA16816(sacc[2*nt2+1], qhf[ks], kl4[1], kl4[3]);
                MMA16816(sacc[2*nt2+1], ql4,     kh4[1], kh4[3]);
            }
        }

        // ---- causal mask (scale folded into q) ----
        int kvbase = kt * 64;
        if (kvbase + 63 > qrow0) {
            #pragma unroll
            for (int nt = 0; nt < 8; nt++) {
                int col = kvbase + 8 * nt + (lane & 3) * 2;
                if (col     > qrow0)     sacc[nt][0] = -1e30f;
                if (col + 1 > qrow0)     sacc[nt][1] = -1e30f;
                if (col     > qrow0 + 8) sacc[nt][2] = -1e30f;
                if (col + 1 > qrow0 + 8) sacc[nt][3] = -1e30f;
            }
        }

        // ---- online softmax ----
        float ml0 = -1e30f, ml1 = -1e30f;
        #pragma unroll
        for (int nt = 0; nt < 8; nt++) {
            ml0 = fmaxf(ml0, fmaxf(sacc[nt][0], sacc[nt][1]));
            ml1 = fmaxf(ml1, fmaxf(sacc[nt][2], sacc[nt][3]));
        }
        ml0 = fmaxf(ml0, __shfl_xor_sync(0xffffffffu, ml0, 1));
        ml0 = fmaxf(ml0, __shfl_xor_sync(0xffffffffu, ml0, 2));
        ml1 = fmaxf(ml1, __shfl_xor_sync(0xffffffffu, ml1, 1));
        ml1 = fmaxf(ml1, __shfl_xor_sync(0xffffffffu, ml1, 2));
        float mn0 = fmaxf(m0, ml0), mn1 = fmaxf(m1, ml1);
        float c0 = __expf(m0 - mn0), c1 = __expf(m1 - mn1);
        float ps0 = 0.f, ps1 = 0.f;
        #pragma unroll
        for (int nt = 0; nt < 8; nt++) {
            sacc[nt][0] = __expf(sacc[nt][0] - mn0);
            sacc[nt][1] = __expf(sacc[nt][1] - mn0);
            sacc[nt][2] = __expf(sacc[nt][2] - mn1);
            sacc[nt][3] = __expf(sacc[nt][3] - mn1);
            ps0 += sacc[nt][0] + sacc[nt][1];
            ps1 += sacc[nt][2] + sacc[nt][3];
        }
        ps0 += __shfl_xor_sync(0xffffffffu, ps0, 1);
        ps0 += __shfl_xor_sync(0xffffffffu, ps0, 2);
        ps1 += __shfl_xor_sync(0xffffffffu, ps1, 1);
        ps1 += __shfl_xor_sync(0xffffffffu, ps1, 2);
        l0 = l0 * c0 + ps0;
        l1 = l1 * c1 + ps1;
        m0 = mn0; m1 = mn1;
        #pragma unroll
        for (int nt = 0; nt < 16; nt++) {
            acc[nt][0] *= c0; acc[nt][1] *= c0;
            acc[nt][2] *= c1; acc[nt][3] *= c1;
        }

        // ---- pack P fragments (hi/lo) ----
        uint32_t ph[4][4], pl[4][4];
        #pragma unroll
        for (int j = 0; j < 4; j++) {
            #pragma unroll
            for (int half = 0; half < 2; half++) {
                float p0 = sacc[2*j+half][0], p1 = sacc[2*j+half][1];
                float p2 = sacc[2*j+half][2], p3 = sacc[2*j+half][3];
                __nv_bfloat16 h0 = __float2bfloat16(p0), h1b = __float2bfloat16(p1);
                __nv_bfloat16 h2 = __float2bfloat16(p2), h3 = __float2bfloat16(p3);
                ph[j][2*half]   = packbf(__bfloat162float(h0), __bfloat162float(h1b));
                ph[j][2*half+1] = packbf(__bfloat162float(h2), __bfloat162float(h3));
                pl[j][2*half]   = packbf(p0 - __bfloat162float(h0), p1 - __bfloat162float(h1b));
                pl[j][2*half+1] = packbf(p2 - __bfloat162float(h2), p3 - __bfloat162float(h3));
            }
        }

        // ---- O += P V ----
        #pragma unroll
        for (int j = 0; j < 4; j++) {
            #pragma unroll
            for (int dt = 0; dt < 8; dt++) {
                int cb = 2 * dt + (lane >> 4);
                uint32_t vd = st + ATT_VH + swz256(16 * j + lrow, cb);
                uint32_t vh4[4], vl4[4];
                LDSM_X4_T(vh4, vd);
                LDSM_X4_T(vl4, vd + (ATT_VL - ATT_VH));
                MMA16816(acc[2*dt],   ph[j], vh4[0], vh4[1]);
                MMA16816(acc[2*dt],   ph[j], vl4[0], vl4[1]);
                MMA16816(acc[2*dt],   pl[j], vh4[0], vh4[1]);
                MMA16816(acc[2*dt+1], ph[j], vh4[2], vh4[3]);
                MMA16816(acc[2*dt+1], ph[j], vl4[2], vl4[3]);
                MMA16816(acc[2*dt+1], pl[j], vh4[2], vh4[3]);
            }
        }
    }

    // ---- epilogue: normalize, split to bf16 hi/lo, write [b*T+t][h*128+d] ----
    float i0 = 1.f / l0, i1 = 1.f / l1;
    const int trow0 = qt * 128 + 16 * w + r4;
    const size_t orow0 = (size_t)(b * T_SEQ + trow0) * 2048 + h * 128;
    const size_t orow1 = orow0 + 8 * 2048;
    #pragma unroll
    for (int nt = 0; nt < 16; nt++) {
        int d = 8 * nt + (lane & 3) * 2;
        float a0 = acc[nt][0] * i0, a1 = acc[nt][1] * i0;
        float a2 = acc[nt][2] * i1, a3 = acc[nt][3] * i1;
        __nv_bfloat16 h0 = __float2bfloat16(a0), h1b = __float2bfloat16(a1);
        __nv_bfloat16 h2 = __float2bfloat16(a2), h3 = __float2bfloat16(a3);
        *(uint32_t*)&oh[orow0 + d] = packbf(__bfloat162float(h0), __bfloat162float(h1b));
        *(uint32_t*)&oh[orow1 + d] = packbf(__bfloat162float(h2), __bfloat162float(h3));
        *(uint32_t*)&ol[orow0 + d] = packbf(a0 - __bfloat162float(h0), a1 - __bfloat162float(h1b));
        *(uint32_t*)&ol[orow1 + d] = packbf(a2 - __bfloat162float(h2), a3 - __bfloat162float(h3));
    }
}

// ---------------- launch ----------------
extern "C" void kernel_launch(void* const* d_in, const int* in_sizes, int n_in,
                              void* d_out, int out_size)
{
    const float* x   = (const float*)d_in[0];
    const float* w_q = (const float*)d_in[1];
    const float* w_k = (const float*)d_in[2];
    const float* w_v = (const float*)d_in[3];
    const float* w_o = (const float*)d_in[4];
    float* out = (float*)d_out;

    float *q, *k, *v;
    __nv_bfloat16 *xh, *xl, *wh, *wl, *woh, *wol, *ah, *al;
    __nv_bfloat16 *qh, *ql, *kh, *kl, *vh, *vl;
    cudaGetSymbolAddress((void**)&q,   g_q);
    cudaGetSymbolAddress((void**)&k,   g_k);
    cudaGetSymbolAddress((void**)&v,   g_v);
    cudaGetSymbolAddress((void**)&xh,  g_xh);
    cudaGetSymbolAddress((void**)&xl,  g_xl);
    cudaGetSymbolAddress((void**)&wh,  g_wh);
    cudaGetSymbolAddress((void**)&wl,  g_wl);
    cudaGetSymbolAddress((void**)&woh, g_woh);
    cudaGetSymbolAddress((void**)&wol, g_wol);
    cudaGetSymbolAddress((void**)&ah,  g_ah);
    cudaGetSymbolAddress((void**)&al,  g_al);
    cudaGetSymbolAddress((void**)&qh,  g_qh);
    cudaGetSymbolAddress((void**)&ql,  g_ql);
    cudaGetSymbolAddress((void**)&kh,  g_kh);
    cudaGetSymbolAddress((void**)&kl,  g_kl);
    cudaGetSymbolAddress((void**)&vh,  g_vh);
    cudaGetSymbolAddress((void**)&vl,  g_vl);

    // input conversions to bf16 hi/lo
    {
        int n4;
        n4 = MROWS * KDIM / 4;
        convert_hilo<<<(n4 + 255) / 256, 256>>>(x, xh, xl, n4);
        n4 = 2048 * KDIM / 4;
        convert_hilo<<<(n4 + 255) / 256, 256>>>(w_q, wh, wl, n4);
        n4 = 512 * KDIM / 4;
        convert_hilo<<<(n4 + 255) / 256, 256>>>(w_k, wh + (size_t)2048 * KDIM, wl + (size_t)2048 * KDIM, n4);
        convert_hilo<<<(n4 + 255) / 256, 256>>>(w_v, wh + (size_t)2560 * KDIM, wl + (size_t)2560 * KDIM, n4);
        n4 = 2048 * KDIM / 4;
        convert_hilo<<<(n4 + 255) / 256, 256>>>(w_o, woh, wol, n4);
    }

    cudaFuncSetAttribute(gemm_mma<0>, cudaFuncAttributeMaxDynamicSharedMemorySize, GEMM_SMEM);
    cudaFuncSetAttribute(gemm_mma<1>, cudaFuncAttributeMaxDynamicSharedMemorySize, GEMM_SMEM);

    // fused QKV projection with scatter epilogue (fp32 q/k/v)
    gemm_mma<1><<<dim3(3072 / 128, MROWS / 128), 256, GEMM_SMEM>>>(xh, xl, wh, wl, q);

    // RoPE -> scaled bf16 hi/lo (scale folded into q), V split
    {
        long qp = (long)B_SZ * N_HEADS * T_SEQ * 64;
        long kp = (long)B_SZ * N_KV   * T_SEQ * 64;
        rope_split<<<(unsigned)((qp + 255) / 256), 256>>>(q, qh, ql, qp, 0.08838834764831845f);
        rope_split<<<(unsigned)((kp + 255) / 256), 256>>>(k, kh, kl, kp, 1.0f);
        int n4 = B_SZ * N_KV * T_SEQ * HD / 4;
        convert_hilo<<<(n4 + 255) / 256, 256>>>(v, vh, vl, n4);
    }

    // tensor-core attention -> g_ah/g_al (bf16 hi/lo, [b*T+t][h*128+d])
    cudaFuncSetAttribute(attn_mma, cudaFuncAttributeMaxDynamicSharedMemorySize, ATT_SMEM);
    attn_mma<<<dim3(T_SEQ / 128, B_SZ * N_HEADS), 256, ATT_SMEM>>>(qh, ql, kh, kl, vh, vl, ah, al);

    // O projection
    gemm_mma<0><<<dim3(2048 / 128, MROWS / 128), 256, GEMM_SMEM>>>(ah, al, woh, wol, out);
}

// round 6
// speedup vs baseline: 1.2729x; 1.2729x over previous
#include <cuda_runtime.h>
#include <cuda_fp16.h>
#include <math.h>
#include <stdint.h>

#define B_SZ    2
#define T_SEQ   2048
#define D_MODEL 2048
#define N_HEADS 16
#define N_KV    4
#define HD      128
#define KDIM    2048
#define MROWS   (B_SZ * T_SEQ)          // 4096

// ---------------- scratch (static device globals; no allocs) ----------------
__device__ float g_q[(size_t)B_SZ * N_HEADS * T_SEQ * HD];
__device__ float g_k[(size_t)B_SZ * N_KV   * T_SEQ * HD];
__device__ float g_v[(size_t)B_SZ * N_KV   * T_SEQ * HD];

__device__ __half g_xh[(size_t)MROWS * KDIM];
__device__ __half g_xl[(size_t)MROWS * KDIM];
__device__ __half g_wF[(size_t)3072 * KDIM];    // wq|wk|wv stacked, single fp16
__device__ __half g_woF[(size_t)2048 * KDIM];   // w_o single fp16
__device__ __half g_ah[(size_t)MROWS * KDIM];   // attention out hi/lo
__device__ __half g_al[(size_t)MROWS * KDIM];

__device__ __half g_qh[(size_t)B_SZ * N_HEADS * T_SEQ * HD];
__device__ __half g_ql[(size_t)B_SZ * N_HEADS * T_SEQ * HD];
__device__ __half g_kh[(size_t)B_SZ * N_KV * T_SEQ * HD];
__device__ __half g_kl[(size_t)B_SZ * N_KV * T_SEQ * HD];
__device__ __half g_vh[(size_t)B_SZ * N_KV * T_SEQ * HD];
__device__ __half g_vl[(size_t)B_SZ * N_KV * T_SEQ * HD];

// ---------------- helpers ----------------
__device__ __forceinline__ uint32_t smem_to_u32(const void* p) {
    uint32_t a;
    asm("{ .reg .u64 t; cvta.to.shared.u64 t, %1; cvt.u32.u64 %0, t; }" : "=r"(a) : "l"(p));
    return a;
}
#define SW128(off) ((off) ^ (((off) >> 3) & 0x70))

__device__ __forceinline__ void cp16(uint32_t saddr, const void* g) {
    asm volatile("cp.async.cg.shared.global [%0], [%1], 16;\n" :: "r"(saddr), "l"(g));
}
#define LDSM_X4(r, a) \
    asm volatile("ldmatrix.sync.aligned.m8n8.x4.shared.b16 {%0,%1,%2,%3}, [%4];" \
        : "=r"((r)[0]), "=r"((r)[1]), "=r"((r)[2]), "=r"((r)[3]) : "r"(a))
#define LDSM_X4_T(r, a) \
    asm volatile("ldmatrix.sync.aligned.m8n8.x4.trans.shared.b16 {%0,%1,%2,%3}, [%4];" \
        : "=r"((r)[0]), "=r"((r)[1]), "=r"((r)[2]), "=r"((r)[3]) : "r"(a))
#define MMA16816(c, a, b0, b1) \
    asm volatile("mma.sync.aligned.m16n8k16.row.col.f32.f16.f16.f32 " \
        "{%0,%1,%2,%3}, {%4,%5,%6,%7}, {%8,%9}, {%0,%1,%2,%3};" \
        : "+f"((c)[0]), "+f"((c)[1]), "+f"((c)[2]), "+f"((c)[3]) \
        : "r"((a)[0]), "r"((a)[1]), "r"((a)[2]), "r"((a)[3]), "r"(b0), "r"(b1))

__device__ __forceinline__ uint32_t packh(float a, float b) {
    __half2 t = __floats2half2_rn(a, b);
    return reinterpret_cast<uint32_t&>(t);
}

// ---------------- fp32 -> fp16 hi/lo split ----------------
__global__ void convert_hilo_h(const float* __restrict__ src,
                               __half* __restrict__ hi,
                               __half* __restrict__ lo, int n4)
{
    int i = blockIdx.x * blockDim.x + threadIdx.x;
    if (i >= n4) return;
    float4 v = ((const float4*)src)[i];
    __half h0 = __float2half_rn(v.x), h1 = __float2half_rn(v.y);
    __half h2 = __float2half_rn(v.z), h3 = __float2half_rn(v.w);
    __half l0 = __float2half_rn(v.x - __half2float(h0));
    __half l1 = __float2half_rn(v.y - __half2float(h1));
    __half l2 = __float2half_rn(v.z - __half2float(h2));
    __half l3 = __float2half_rn(v.w - __half2float(h3));
    ((__half2*)hi)[2 * i]     = __half2(h0, h1);
    ((__half2*)hi)[2 * i + 1] = __half2(h2, h3);
    ((__half2*)lo)[2 * i]     = __half2(l0, l1);
    ((__half2*)lo)[2 * i + 1] = __half2(l2, l3);
}

// ---------------- fp32 -> fp16 single ----------------
__global__ void convert_h(const float* __restrict__ src, __half* __restrict__ dst, int n4)
{
    int i = blockIdx.x * blockDim.x + threadIdx.x;
    if (i >= n4) return;
    float4 v = ((const float4*)src)[i];
    ((__half2*)dst)[2 * i]     = __floats2half2_rn(v.x, v.y);
    ((__half2*)dst)[2 * i + 1] = __floats2half2_rn(v.z, v.w);
}

// ---------------- 2-product fp16 GEMM: C = (Ah+Al) @ Bf^T ----------------
// A = activations split hi/lo fp16, B = weights single fp16.
// Tile 128x128, BK=64, 3-stage ring, 1 barrier per chunk.
#define OFF_AH 0
#define OFF_AL 16384
#define OFF_B  32768
#define STAGE_BYTES 49152
#define GEMM_SMEM (3 * STAGE_BYTES)     // 147456

template<int MODE>
__global__ __launch_bounds__(256, 1)
void gemm2p(const __half* __restrict__ Ah, const __half* __restrict__ Al,
            const __half* __restrict__ Bf, float* __restrict__ C)
{
    extern __shared__ __align__(1024) char smem[];
    const uint32_t sb = smem_to_u32(smem);
    const int tid  = threadIdx.x;
    const int lane = tid & 31;
    const int wid  = tid >> 5;
    const int warp_m = (wid & 3) * 32;
    const int warp_n = (wid >> 2) * 64;
    const int bm0 = blockIdx.y * 128;
    const int bn0 = blockIdx.x * 128;

    float acc[2][8][4];
    #pragma unroll
    for (int mt = 0; mt < 2; mt++)
        #pragma unroll
        for (int nt = 0; nt < 8; nt++)
            #pragma unroll
            for (int i = 0; i < 4; i++) acc[mt][nt][i] = 0.f;

    auto load_chunk = [&](int c) {
        uint32_t st = sb + (uint32_t)(c % 3) * STAGE_BYTES;
        int k0 = c * 64;
        #pragma unroll
        for (int j = 0; j < 4; j++) {
            int i = tid + j * 256;
            int row = i >> 3, cb = (i & 7) * 16;
            uint32_t so = SW128((uint32_t)(row * 128 + cb));
            size_t goA = ((size_t)(bm0 + row) * KDIM + k0) * 2 + cb;
            size_t goB = ((size_t)(bn0 + row) * KDIM + k0) * 2 + cb;
            cp16(st + OFF_AH + so, (const char*)Ah + goA);
            cp16(st + OFF_AL + so, (const char*)Al + goA);
            cp16(st + OFF_B  + so, (const char*)Bf + goB);
        }
        asm volatile("cp.async.commit_group;\n");
    };

    load_chunk(0);
    load_chunk(1);

    const int NC = KDIM / 64;
    for (int c = 0; c < NC; c++) {
        if (c == NC - 1) asm volatile("cp.async.wait_group 0;\n");
        else             asm volatile("cp.async.wait_group 1;\n");
        __syncthreads();
        if (c + 2 < NC) load_chunk(c + 2);

        uint32_t st = sb + (uint32_t)(c % 3) * STAGE_BYTES;
        #pragma unroll
        for (int ks = 0; ks < 4; ks++) {
            uint32_t ah[2][4], al[2][4], bh[4][4];
            int lrow = (lane & 7) + ((lane >> 3) & 1) * 8;
            int lcb  = ks * 32 + (lane >> 4) * 16;
            #pragma unroll
            for (int mt = 0; mt < 2; mt++) {
                int arow = warp_m + mt * 16 + lrow;
                uint32_t ad = st + OFF_AH + SW128((uint32_t)(arow * 128 + lcb));
                LDSM_X4(ah[mt], ad);
                LDSM_X4(al[mt], ad + (OFF_AL - OFF_AH));
            }
            #pragma unroll
            for (int nt = 0; nt < 4; nt++) {
                int brow = warp_n + nt * 16 + lrow;
                LDSM_X4(bh[nt], st + OFF_B + SW128((uint32_t)(brow * 128 + lcb)));
            }
            #pragma unroll
            for (int mt = 0; mt < 2; mt++) {
                #pragma unroll
                for (int nt4 = 0; nt4 < 4; nt4++) {
                    MMA16816(acc[mt][2*nt4],   ah[mt], bh[nt4][0], bh[nt4][2]);
                    MMA16816(acc[mt][2*nt4],   al[mt], bh[nt4][0], bh[nt4][2]);
                    MMA16816(acc[mt][2*nt4+1], ah[mt], bh[nt4][1], bh[nt4][3]);
                    MMA16816(acc[mt][2*nt4+1], al[mt], bh[nt4][1], bh[nt4][3]);
                }
            }
        }
    }

    const int rbase = bm0 + warp_m + (lane >> 2);
    const int cbase = bn0 + warp_n + (lane & 3) * 2;
    #pragma unroll
    for (int mt = 0; mt < 2; mt++) {
        #pragma unroll
        for (int hh = 0; hh < 2; hh++) {
            int row = rbase + mt * 16 + hh * 8;
            #pragma unroll
            for (int nt = 0; nt < 8; nt++) {
                int col = cbase + nt * 8;
                float2 v = make_float2(acc[mt][nt][2*hh], acc[mt][nt][2*hh+1]);
                if (MODE == 0) {
                    *(float2*)&C[(size_t)row * 2048 + col] = v;
                } else {
                    int b = row >> 11, tq = row & (T_SEQ - 1), d = col & 127;
                    float* base;
                    if (col < 2048) {
                        int h = col >> 7;
                        base = g_q + (((size_t)(b * N_HEADS + h) * T_SEQ + tq) * HD + d);
                    } else if (col < 2560) {
                        int h = (col - 2048) >> 7;
                        base = g_k + (((size_t)(b * N_KV + h) * T_SEQ + tq) * HD + d);
                    } else {
                        int h = (col - 2560) >> 7;
                        base = g_v + (((size_t)(b * N_KV + h) * T_SEQ + tq) * HD + d);
                    }
                    *(float2*)base = v;
                }
            }
        }
    }
}

// ---------------- RoPE: fp32 in -> rotated, scaled fp16 hi/lo out ----------------
__global__ void rope_split_h(const float* __restrict__ src,
                             __half* __restrict__ hi,
                             __half* __restrict__ lo,
                             long total_pairs, float scale)
{
    long idx = (long)blockIdx.x * blockDim.x + threadIdx.x;
    if (idx >= total_pairs) return;
    int  i   = (int)(idx & 63);
    long row = idx >> 6;
    int  tpos = (int)(row & (T_SEQ - 1));
    const float* p = src + row * HD;
    float inv = __expf(-((float)i / 64.0f) * 13.815510557964274f);
    float s, c;
    sincosf((float)tpos * inv, &s, &c);
    float x1 = p[i], x2 = p[i + 64];
    float r1 = (x1 * c - x2 * s) * scale;
    float r2 = (x2 * c + x1 * s) * scale;
    __half h1 = __float2half_rn(r1), h2 = __float2half_rn(r2);
    hi[row * HD + i]      = h1;
    hi[row * HD + i + 64] = h2;
    lo[row * HD + i]      = __float2half_rn(r1 - __half2float(h1));
    lo[row * HD + i + 64] = __float2half_rn(r2 - __half2float(h2));
}

// ---------------- tensor-core flash attention (split-fp16 3-product) ----------
#define ATT_QL    0
#define ATT_ST0   32768
#define ATT_STAGE 65536
#define ATT_KH 0
#define ATT_KL 16384
#define ATT_VH 32768
#define ATT_VL 49152
#define ATT_SMEM (ATT_ST0 + 3 * ATT_STAGE)   // 229376

__device__ __forceinline__ uint32_t swz256(int row, int cb) {
    return (uint32_t)(row * 256 + ((cb ^ (row & 7)) << 4));
}

__global__ __launch_bounds__(256, 1)
void attn_mma(const __half* __restrict__ qh, const __half* __restrict__ ql,
              const __half* __restrict__ kh, const __half* __restrict__ kl,
              const __half* __restrict__ vh, const __half* __restrict__ vl,
              __half* __restrict__ oh, __half* __restrict__ ol)
{
    extern __shared__ __align__(1024) char smem[];
    const uint32_t sb = smem_to_u32(smem);
    const int tid  = threadIdx.x;
    const int w    = tid >> 5;
    const int lane = tid & 31;
    const int qt   = (gridDim.x - 1) - blockIdx.x;
    const int bh   = blockIdx.y;
    const int b    = bh >> 4;
    const int h    = bh & 15;
    const int kvh  = h >> 2;

    const size_t qoff = ((size_t)bh * T_SEQ + (size_t)qt * 128) * HD;
    const size_t koff = (size_t)(b * N_KV + kvh) * T_SEQ * HD;

    const int r4 = lane >> 2;
    const int lrow = (lane & 7) + ((lane >> 3) & 1) * 8;

    // ---- preamble: Q-hi (temp, stage0 region) + Q-lo (persistent) ----
    #pragma unroll
    for (int j = 0; j < 8; j++) {
        int i = tid + j * 256;
        int row = i >> 4, cb = i & 15;
        uint32_t so = swz256(row, cb);
        size_t go = (qoff + (size_t)row * HD) * 2 + cb * 16;
        cp16(sb + ATT_ST0 + so, (const char*)qh + go);
        cp16(sb + ATT_QL  + so, (const char*)ql + go);
    }
    asm volatile("cp.async.commit_group;\n");
    asm volatile("cp.async.wait_group 0;\n");
    __syncthreads();

    uint32_t qhf[8][4];
    #pragma unroll
    for (int ks = 0; ks < 8; ks++) {
        int cb = 2 * ks + (lane >> 4);
        LDSM_X4(qhf[ks], sb + ATT_ST0 + swz256(16 * w + lrow, cb));
    }
    __syncthreads();

    auto load_stage = [&](int kt) {
        uint32_t st = sb + ATT_ST0 + (uint32_t)(kt % 3) * ATT_STAGE;
        size_t base = (koff + (size_t)kt * 64 * HD) * 2;
        #pragma unroll
        for (int j = 0; j < 4; j++) {
            int i = tid + j * 256;
            int row = i >> 4, cb = i & 15;
            uint32_t so = swz256(row, cb);
            size_t go = base + (size_t)row * 256 + cb * 16;
            cp16(st + ATT_KH + so, (const char*)kh + go);
            cp16(st + ATT_KL + so, (const char*)kl + go);
            cp16(st + ATT_VH + so, (const char*)vh + go);
            cp16(st + ATT_VL + so, (const char*)vl + go);
        }
        asm volatile("cp.async.commit_group;\n");
    };

    const int nkt = 2 * (qt + 1);
    load_stage(0);
    load_stage(1);

    float acc[16][4];
    #pragma unroll
    for (int nt = 0; nt < 16; nt++)
        #pragma unroll
        for (int i = 0; i < 4; i++) acc[nt][i] = 0.f;
    float m0 = -1e30f, m1 = -1e30f, l0 = 0.f, l1 = 0.f;

    const int qrow0 = qt * 128 + 16 * w + r4;
    const int wmax  = qt * 128 + 16 * w + 15;   // max q-row this warp owns

    for (int kt = 0; kt < nkt; kt++) {
        if (kt == nkt - 1) asm volatile("cp.async.wait_group 0;\n");
        else               asm volatile("cp.async.wait_group 1;\n");
        __syncthreads();
        if (kt + 2 < nkt) load_stage(kt + 2);

        int kvbase = kt * 64;
        if (kvbase > wmax) continue;   // whole warp masked; barriers already passed
        uint32_t st = sb + ATT_ST0 + (uint32_t)(kt % 3) * ATT_STAGE;

        // ---- S = Q K^T (3-product fp16) ----
        float sacc[8][4];
        #pragma unroll
        for (int nt = 0; nt < 8; nt++)
            #pragma unroll
            for (int i = 0; i < 4; i++) sacc[nt][i] = 0.f;

        #pragma unroll
        for (int ks = 0; ks < 8; ks++) {
            int cb = 2 * ks + (lane >> 4);
            uint32_t ql4[4];
            LDSM_X4(ql4, sb + ATT_QL + swz256(16 * w + lrow, cb));
            #pragma unroll
            for (int nt2 = 0; nt2 < 4; nt2++) {
                uint32_t bd = st + ATT_KH + swz256(16 * nt2 + lrow, cb);
                uint32_t kh4[4], kl4[4];
                LDSM_X4(kh4, bd);
                LDSM_X4(kl4, bd + (ATT_KL - ATT_KH));
                MMA16816(sacc[2*nt2],   qhf[ks], kh4[0], kh4[2]);
                MMA16816(sacc[2*nt2],   qhf[ks], kl4[0], kl4[2]);
                MMA16816(sacc[2*nt2],   ql4,     kh4[0], kh4[2]);
                MMA16816(sacc[2*nt2+1], qhf[ks], kh4[1], kh4[3]);
                MMA16816(sacc[2*nt2+1], qhf[ks], kl4[1], kl4[3]);
                MMA16816(sacc[2*nt2+1], ql4,     kh4[1], kh4[3]);
            }
        }

        // ---- causal mask ----
        if (kvbase + 63 > qrow0) {
            #pragma unroll
            for (int nt = 0; nt < 8; nt++) {
                int col = kvbase + 8 * nt + (lane & 3) * 2;
                if (col     > qrow0)     sacc[nt][0] = -1e30f;
                if (col + 1 > qrow0)     sacc[nt][1] = -1e30f;
                if (col     > qrow0 + 8) sacc[nt][2] = -1e30f;
                if (col + 1 > qrow0 + 8) sacc[nt][3] = -1e30f;
            }
        }

        // ---- online softmax ----
        float ml0 = -1e30f, ml1 = -1e30f;
        #pragma unroll
        for (int nt = 0; nt < 8; nt++) {
            ml0 = fmaxf(ml0, fmaxf(sacc[nt][0], sacc[nt][1]));
            ml1 = fmaxf(ml1, fmaxf(sacc[nt][2], sacc[nt][3]));
        }
        ml0 = fmaxf(ml0, __shfl_xor_sync(0xffffffffu, ml0, 1));
        ml0 = fmaxf(ml0, __shfl_xor_sync(0xffffffffu, ml0, 2));
        ml1 = fmaxf(ml1, __shfl_xor_sync(0xffffffffu, ml1, 1));
        ml1 = fmaxf(ml1, __shfl_xor_sync(0xffffffffu, ml1, 2));
        float mn0 = fmaxf(m0, ml0), mn1 = fmaxf(m1, ml1);
        float c0 = __expf(m0 - mn0), c1 = __expf(m1 - mn1);
        float ps0 = 0.f, ps1 = 0.f;
        #pragma unroll
        for (int nt = 0; nt < 8; nt++) {
            sacc[nt][0] = __expf(sacc[nt][0] - mn0);
            sacc[nt][1] = __expf(sacc[nt][1] - mn0);
            sacc[nt][2] = __expf(sacc[nt][2] - mn1);
            sacc[nt][3] = __expf(sacc[nt][3] - mn1);
            ps0 += sacc[nt][0] + sacc[nt][1];
            ps1 += sacc[nt][2] + sacc[nt][3];
        }
        ps0 += __shfl_xor_sync(0xffffffffu, ps0, 1);
        ps0 += __shfl_xor_sync(0xffffffffu, ps0, 2);
        ps1 += __shfl_xor_sync(0xffffffffu, ps1, 1);
        ps1 += __shfl_xor_sync(0xffffffffu, ps1, 2);
        l0 = l0 * c0 + ps0;
        l1 = l1 * c1 + ps1;
        m0 = mn0; m1 = mn1;
        #pragma unroll
        for (int nt = 0; nt < 16; nt++) {
            acc[nt][0] *= c0; acc[nt][1] *= c0;
            acc[nt][2] *= c1; acc[nt][3] *= c1;
        }

        // ---- pack P fragments (fp16 hi/lo) ----
        uint32_t ph[4][4], pl[4][4];
        #pragma unroll
        for (int j = 0; j < 4; j++) {
            #pragma unroll
            for (int half = 0; half < 2; half++) {
                float p0 = sacc[2*j+half][0], p1 = sacc[2*j+half][1];
                float p2 = sacc[2*j+half][2], p3 = sacc[2*j+half][3];
                __half h0 = __float2half_rn(p0), h1b = __float2half_rn(p1);
                __half h2 = __float2half_rn(p2), h3 = __float2half_rn(p3);
                ph[j][2*half]   = packh(__half2float(h0), __half2float(h1b));
                ph[j][2*half+1] = packh(__half2float(h2), __half2float(h3));
                pl[j][2*half]   = packh(p0 - __half2float(h0), p1 - __half2float(h1b));
                pl[j][2*half+1] = packh(p2 - __half2float(h2), p3 - __half2float(h3));
            }
        }

        // ---- O += P V (3-product fp16) ----
        #pragma unroll
        for (int j = 0; j < 4; j++) {
            #pragma unroll
            for (int dt = 0; dt < 8; dt++) {
                int cb = 2 * dt + (lane >> 4);
                uint32_t vd = st + ATT_VH + swz256(16 * j + lrow, cb);
                uint32_t vh4[4], vl4[4];
                LDSM_X4_T(vh4, vd);
                LDSM_X4_T(vl4, vd + (ATT_VL - ATT_VH));
                MMA16816(acc[2*dt],   ph[j], vh4[0], vh4[1]);
                MMA16816(acc[2*dt],   ph[j], vl4[0], vl4[1]);
                MMA16816(acc[2*dt],   pl[j], vh4[0], vh4[1]);
                MMA16816(acc[2*dt+1], ph[j], vh4[2], vh4[3]);
                MMA16816(acc[2*dt+1], ph[j], vl4[2], vl4[3]);
                MMA16816(acc[2*dt+1], pl[j], vh4[2], vh4[3]);
            }
        }
    }

    // ---- epilogue: normalize, split to fp16 hi/lo, write [b*T+t][h*128+d] ----
    float i0 = 1.f / l0, i1 = 1.f / l1;
    const int trow0 = qt * 128 + 16 * w + r4;
    const size_t orow0 = (size_t)(b * T_SEQ + trow0) * 2048 + h * 128;
    const size_t orow1 = orow0 + 8 * 2048;
    #pragma unroll
    for (int nt = 0; nt < 16; nt++) {
        int d = 8 * nt + (lane & 3) * 2;
        float a0 = acc[nt][0] * i0, a1 = acc[nt][1] * i0;
        float a2 = acc[nt][2] * i1, a3 = acc[nt][3] * i1;
        __half h0 = __float2half_rn(a0), h1b = __float2half_rn(a1);
        __half h2 = __float2half_rn(a2), h3 = __float2half_rn(a3);
        *(uint32_t*)&oh[orow0 + d] = packh(__half2float(h0), __half2float(h1b));
        *(uint32_t*)&oh[orow1 + d] = packh(__half2float(h2), __half2float(h3));
        *(uint32_t*)&ol[orow0 + d] = packh(a0 - __half2float(h0), a1 - __half2float(h1b));
        *(uint32_t*)&ol[orow1 + d] = packh(a2 - __half2float(h2), a3 - __half2float(h3));
    }
}

// ---------------- launch ----------------
extern "C" void kernel_launch(void* const* d_in, const int* in_sizes, int n_in,
                              void* d_out, int out_size)
{
    const float* x   = (const float*)d_in[0];
    const float* w_q = (const float*)d_in[1];
    const float* w_k = (const float*)d_in[2];
    const float* w_v = (const float*)d_in[3];
    const float* w_o = (const float*)d_in[4];
    float* out = (float*)d_out;

    float *q, *k, *v;
    __half *xh, *xl, *wF, *woF, *ah, *al;
    __half *qh, *ql, *kh, *kl, *vh, *vl;
    cudaGetSymbolAddress((void**)&q,   g_q);
    cudaGetSymbolAddress((void**)&k,   g_k);
    cudaGetSymbolAddress((void**)&v,   g_v);
    cudaGetSymbolAddress((void**)&xh,  g_xh);
    cudaGetSymbolAddress((void**)&xl,  g_xl);
    cudaGetSymbolAddress((void**)&wF,  g_wF);
    cudaGetSymbolAddress((void**)&woF, g_woF);
    cudaGetSymbolAddress((void**)&ah,  g_ah);
    cudaGetSymbolAddress((void**)&al,  g_al);
    cudaGetSymbolAddress((void**)&qh,  g_qh);
    cudaGetSymbolAddress((void**)&ql,  g_ql);
    cudaGetSymbolAddress((void**)&kh,  g_kh);
    cudaGetSymbolAddress((void**)&kl,  g_kl);
    cudaGetSymbolAddress((void**)&vh,  g_vh);
    cudaGetSymbolAddress((void**)&vl,  g_vl);

    // input conversions
    {
        int n4;
        n4 = MROWS * KDIM / 4;
        convert_hilo_h<<<(n4 + 255) / 256, 256>>>(x, xh, xl, n4);
        n4 = 2048 * KDIM / 4;
        convert_h<<<(n4 + 255) / 256, 256>>>(w_q, wF, n4);
        n4 = 512 * KDIM / 4;
        convert_h<<<(n4 + 255) / 256, 256>>>(w_k, wF + (size_t)2048 * KDIM, n4);
        convert_h<<<(n4 + 255) / 256, 256>>>(w_v, wF + (size_t)2560 * KDIM, n4);
        n4 = 2048 * KDIM / 4;
        convert_h<<<(n4 + 255) / 256, 256>>>(w_o, woF, n4);
    }

    cudaFuncSetAttribute(gemm2p<0>, cudaFuncAttributeMaxDynamicSharedMemorySize, GEMM_SMEM);
    cudaFuncSetAttribute(gemm2p<1>, cudaFuncAttributeMaxDynamicSharedMemorySize, GEMM_SMEM);

    // fused QKV projection with scatter epilogue (fp32 q/k/v)
    gemm2p<1><<<dim3(3072 / 128, MROWS / 128), 256, GEMM_SMEM>>>(xh, xl, wF, q);

    // RoPE -> scaled fp16 hi/lo (scale folded into q), V split
    {
        long qp = (long)B_SZ * N_HEADS * T_SEQ * 64;
        long kp = (long)B_SZ * N_KV   * T_SEQ * 64;
        rope_split_h<<<(unsigned)((qp + 255) / 256), 256>>>(q, qh, ql, qp, 0.08838834764831845f);
        rope_split_h<<<(unsigned)((kp + 255) / 256), 256>>>(k, kh, kl, kp, 1.0f);
        int n4 = B_SZ * N_KV * T_SEQ * HD / 4;
        convert_hilo_h<<<(n4 + 255) / 256, 256>>>(v, vh, vl, n4);
    }

    // tensor-core attention -> g_ah/g_al (fp16 hi/lo, [b*T+t][h*128+d])
    cudaFuncSetAttribute(attn_mma, cudaFuncAttributeMaxDynamicSharedMemorySize, ATT_SMEM);
    attn_mma<<<dim3(T_SEQ / 128, B_SZ * N_HEADS), 256, ATT_SMEM>>>(qh, ql, kh, kl, vh, vl, ah, al);

    // O projection (2-product fp16)
    gemm2p<0><<<dim3(2048 / 128, MROWS / 128), 256, GEMM_SMEM>>>(ah, al, woF, out);
}

// round 7
// speedup vs baseline: 1.6019x; 1.2584x over previous
#include <cuda_runtime.h>
#include <cuda_fp16.h>
#include <math.h>
#include <stdint.h>

#define B_SZ    2
#define T_SEQ   2048
#define D_MODEL 2048
#define N_HEADS 16
#define N_KV    4
#define HD      128
#define KDIM    2048
#define MROWS   (B_SZ * T_SEQ)          // 4096

// ---------------- scratch (static device globals; no allocs) ----------------
__device__ float g_q[(size_t)B_SZ * N_HEADS * T_SEQ * HD];
__device__ float g_k[(size_t)B_SZ * N_KV   * T_SEQ * HD];

__device__ __half g_xF[(size_t)MROWS * KDIM];   // x single fp16
__device__ __half g_wF[(size_t)3072 * KDIM];    // wq|wk|wv stacked, single fp16
__device__ __half g_woF[(size_t)2048 * KDIM];   // w_o single fp16
__device__ __half g_ah[(size_t)MROWS * KDIM];   // attention out hi/lo
__device__ __half g_al[(size_t)MROWS * KDIM];

__device__ __half g_qh[(size_t)B_SZ * N_HEADS * T_SEQ * HD];
__device__ __half g_ql[(size_t)B_SZ * N_HEADS * T_SEQ * HD];
__device__ __half g_kh[(size_t)B_SZ * N_KV * T_SEQ * HD];
__device__ __half g_kl[(size_t)B_SZ * N_KV * T_SEQ * HD];
__device__ __half g_vF[(size_t)B_SZ * N_KV * T_SEQ * HD];   // v single fp16

// ---------------- helpers ----------------
__device__ __forceinline__ uint32_t smem_to_u32(const void* p) {
    uint32_t a;
    asm("{ .reg .u64 t; cvta.to.shared.u64 t, %1; cvt.u32.u64 %0, t; }" : "=r"(a) : "l"(p));
    return a;
}
#define SW128(off) ((off) ^ (((off) >> 3) & 0x70))

__device__ __forceinline__ void cp16(uint32_t saddr, const void* g) {
    asm volatile("cp.async.cg.shared.global [%0], [%1], 16;\n" :: "r"(saddr), "l"(g));
}
#define LDSM_X4(r, a) \
    asm volatile("ldmatrix.sync.aligned.m8n8.x4.shared.b16 {%0,%1,%2,%3}, [%4];" \
        : "=r"((r)[0]), "=r"((r)[1]), "=r"((r)[2]), "=r"((r)[3]) : "r"(a))
#define LDSM_X4_T(r, a) \
    asm volatile("ldmatrix.sync.aligned.m8n8.x4.trans.shared.b16 {%0,%1,%2,%3}, [%4];" \
        : "=r"((r)[0]), "=r"((r)[1]), "=r"((r)[2]), "=r"((r)[3]) : "r"(a))
#define MMA16816(c, a, b0, b1) \
    asm volatile("mma.sync.aligned.m16n8k16.row.col.f32.f16.f16.f32 " \
        "{%0,%1,%2,%3}, {%4,%5,%6,%7}, {%8,%9}, {%0,%1,%2,%3};" \
        : "+f"((c)[0]), "+f"((c)[1]), "+f"((c)[2]), "+f"((c)[3]) \
        : "r"((a)[0]), "r"((a)[1]), "r"((a)[2]), "r"((a)[3]), "r"(b0), "r"(b1))

__device__ __forceinline__ uint32_t packh(float a, float b) {
    __half2 t = __floats2half2_rn(a, b);
    return reinterpret_cast<uint32_t&>(t);
}

// ---------------- fp32 -> fp16 hi/lo split ----------------
__global__ void convert_hilo_h(const float* __restrict__ src,
                               __half* __restrict__ hi,
                               __half* __restrict__ lo, int n4)
{
    int i = blockIdx.x * blockDim.x + threadIdx.x;
    if (i >= n4) return;
    float4 v = ((const float4*)src)[i];
    __half h0 = __float2half_rn(v.x), h1 = __float2half_rn(v.y);
    __half h2 = __float2half_rn(v.z), h3 = __float2half_rn(v.w);
    __half l0 = __float2half_rn(v.x - __half2float(h0));
    __half l1 = __float2half_rn(v.y - __half2float(h1));
    __half l2 = __float2half_rn(v.z - __half2float(h2));
    __half l3 = __float2half_rn(v.w - __half2float(h3));
    ((__half2*)hi)[2 * i]     = __half2(h0, h1);
    ((__half2*)hi)[2 * i + 1] = __half2(h2, h3);
    ((__half2*)lo)[2 * i]     = __half2(l0, l1);
    ((__half2*)lo)[2 * i + 1] = __half2(l2, l3);
}

// ---------------- fp32 -> fp16 single ----------------
__global__ void convert_h(const float* __restrict__ src, __half* __restrict__ dst, int n4)
{
    int i = blockIdx.x * blockDim.x + threadIdx.x;
    if (i >= n4) return;
    float4 v = ((const float4*)src)[i];
    ((__half2*)dst)[2 * i]     = __floats2half2_rn(v.x, v.y);
    ((__half2*)dst)[2 * i + 1] = __floats2half2_rn(v.z, v.w);
}

// ---------------- fp16 GEMM: C = (A [+ Al]) @ B^T ----------------
// NPROD=1: A single. NPROD=2: A split hi/lo. B always single fp16.
// Tile 128x128, BK=64, 3-stage ring, 1 barrier per chunk.
// MODE 0: C row-major N=2048.  MODE 1: QKV scatter (q,k fp32; v fp16 direct).
#define OFF_AH 0
#define OFF_AL 16384
#define OFF_B  32768
#define STAGE_BYTES 49152
#define GEMM_SMEM (3 * STAGE_BYTES)     // 147456

template<int MODE, int NPROD>
__global__ __launch_bounds__(256, 1)
void gemm_fp16(const __half* __restrict__ Ah, const __half* __restrict__ Al,
               const __half* __restrict__ Bf, float* __restrict__ C)
{
    extern __shared__ __align__(1024) char smem[];
    const uint32_t sb = smem_to_u32(smem);
    const int tid  = threadIdx.x;
    const int lane = tid & 31;
    const int wid  = tid >> 5;
    const int warp_m = (wid & 3) * 32;
    const int warp_n = (wid >> 2) * 64;
    const int bm0 = blockIdx.y * 128;
    const int bn0 = blockIdx.x * 128;

    float acc[2][8][4];
    #pragma unroll
    for (int mt = 0; mt < 2; mt++)
        #pragma unroll
        for (int nt = 0; nt < 8; nt++)
            #pragma unroll
            for (int i = 0; i < 4; i++) acc[mt][nt][i] = 0.f;

    auto load_chunk = [&](int c) {
        uint32_t st = sb + (uint32_t)(c % 3) * STAGE_BYTES;
        int k0 = c * 64;
        #pragma unroll
        for (int j = 0; j < 4; j++) {
            int i = tid + j * 256;
            int row = i >> 3, cb = (i & 7) * 16;
            uint32_t so = SW128((uint32_t)(row * 128 + cb));
            size_t goA = ((size_t)(bm0 + row) * KDIM + k0) * 2 + cb;
            size_t goB = ((size_t)(bn0 + row) * KDIM + k0) * 2 + cb;
            cp16(st + OFF_AH + so, (const char*)Ah + goA);
            if (NPROD == 2) cp16(st + OFF_AL + so, (const char*)Al + goA);
            cp16(st + OFF_B  + so, (const char*)Bf + goB);
        }
        asm volatile("cp.async.commit_group;\n");
    };

    load_chunk(0);
    load_chunk(1);

    const int NC = KDIM / 64;
    for (int c = 0; c < NC; c++) {
        if (c == NC - 1) asm volatile("cp.async.wait_group 0;\n");
        else             asm volatile("cp.async.wait_group 1;\n");
        __syncthreads();
        if (c + 2 < NC) load_chunk(c + 2);

        uint32_t st = sb + (uint32_t)(c % 3) * STAGE_BYTES;
        #pragma unroll
        for (int ks = 0; ks < 4; ks++) {
            uint32_t ah[2][4], al[2][4], bh[4][4];
            int lrow = (lane & 7) + ((lane >> 3) & 1) * 8;
            int lcb  = ks * 32 + (lane >> 4) * 16;
            #pragma unroll
            for (int mt = 0; mt < 2; mt++) {
                int arow = warp_m + mt * 16 + lrow;
                uint32_t ad = st + OFF_AH + SW128((uint32_t)(arow * 128 + lcb));
                LDSM_X4(ah[mt], ad);
                if (NPROD == 2) LDSM_X4(al[mt], ad + (OFF_AL - OFF_AH));
            }
            #pragma unroll
            for (int nt = 0; nt < 4; nt++) {
                int brow = warp_n + nt * 16 + lrow;
                LDSM_X4(bh[nt], st + OFF_B + SW128((uint32_t)(brow * 128 + lcb)));
            }
            #pragma unroll
            for (int mt = 0; mt < 2; mt++) {
                #pragma unroll
                for (int nt4 = 0; nt4 < 4; nt4++) {
                    MMA16816(acc[mt][2*nt4],   ah[mt], bh[nt4][0], bh[nt4][2]);
                    if (NPROD == 2) MMA16816(acc[mt][2*nt4], al[mt], bh[nt4][0], bh[nt4][2]);
                    MMA16816(acc[mt][2*nt4+1], ah[mt], bh[nt4][1], bh[nt4][3]);
                    if (NPROD == 2) MMA16816(acc[mt][2*nt4+1], al[mt], bh[nt4][1], bh[nt4][3]);
                }
            }
        }
    }

    const int rbase = bm0 + warp_m + (lane >> 2);
    const int cbase = bn0 + warp_n + (lane & 3) * 2;
    #pragma unroll
    for (int mt = 0; mt < 2; mt++) {
        #pragma unroll
        for (int hh = 0; hh < 2; hh++) {
            int row = rbase + mt * 16 + hh * 8;
            #pragma unroll
            for (int nt = 0; nt < 8; nt++) {
                int col = cbase + nt * 8;
                float2 v = make_float2(acc[mt][nt][2*hh], acc[mt][nt][2*hh+1]);
                if (MODE == 0) {
                    *(float2*)&C[(size_t)row * 2048 + col] = v;
                } else {
                    int b = row >> 11, tq = row & (T_SEQ - 1), d = col & 127;
                    if (col < 2048) {
                        int h = col >> 7;
                        float* base = g_q + (((size_t)(b * N_HEADS + h) * T_SEQ + tq) * HD + d);
                        *(float2*)base = v;
                    } else if (col < 2560) {
                        int h = (col - 2048) >> 7;
                        float* base = g_k + (((size_t)(b * N_KV + h) * T_SEQ + tq) * HD + d);
                        *(float2*)base = v;
                    } else {
                        int h = (col - 2560) >> 7;
                        size_t idx = ((size_t)(b * N_KV + h) * T_SEQ + tq) * HD + d;
                        *(uint32_t*)&g_vF[idx] = packh(v.x, v.y);
                    }
                }
            }
        }
    }
}

// ---------------- RoPE: fp32 in -> rotated, scaled fp16 hi/lo out ----------------
__global__ void rope_split_h(const float* __restrict__ src,
                             __half* __restrict__ hi,
                             __half* __restrict__ lo,
                             long total_pairs, float scale)
{
    long idx = (long)blockIdx.x * blockDim.x + threadIdx.x;
    if (idx >= total_pairs) return;
    int  i   = (int)(idx & 63);
    long row = idx >> 6;
    int  tpos = (int)(row & (T_SEQ - 1));
    const float* p = src + row * HD;
    float inv = __expf(-((float)i / 64.0f) * 13.815510557964274f);
    float s, c;
    sincosf((float)tpos * inv, &s, &c);
    float x1 = p[i], x2 = p[i + 64];
    float r1 = (x1 * c - x2 * s) * scale;
    float r2 = (x2 * c + x1 * s) * scale;
    __half h1 = __float2half_rn(r1), h2 = __float2half_rn(r2);
    hi[row * HD + i]      = h1;
    hi[row * HD + i + 64] = h2;
    lo[row * HD + i]      = __float2half_rn(r1 - __half2float(h1));
    lo[row * HD + i + 64] = __float2half_rn(r2 - __half2float(h2));
}

// ---------------- tensor-core flash attention ----------
// QK 3-product (q,k split hi/lo); PV 2-product (P split, V single fp16).
#define ATT_QL    0
#define ATT_ST0   32768
#define ATT_STAGE 49152
#define ATT_KH 0
#define ATT_KL 16384
#define ATT_VF 32768
#define ATT_SMEM (ATT_ST0 + 3 * ATT_STAGE)   // 180224

__device__ __forceinline__ uint32_t swz256(int row, int cb) {
    return (uint32_t)(row * 256 + ((cb ^ (row & 7)) << 4));
}

__global__ __launch_bounds__(256, 1)
void attn_mma(const __half* __restrict__ qh, const __half* __restrict__ ql,
              const __half* __restrict__ kh, const __half* __restrict__ kl,
              const __half* __restrict__ vf,
              __half* __restrict__ oh, __half* __restrict__ ol)
{
    extern __shared__ __align__(1024) char smem[];
    const uint32_t sb = smem_to_u32(smem);
    const int tid  = threadIdx.x;
    const int w    = tid >> 5;
    const int lane = tid & 31;
    const int qt   = (gridDim.x - 1) - blockIdx.x;
    const int bh   = blockIdx.y;
    const int b    = bh >> 4;
    const int h    = bh & 15;
    const int kvh  = h >> 2;

    const size_t qoff = ((size_t)bh * T_SEQ + (size_t)qt * 128) * HD;
    const size_t koff = (size_t)(b * N_KV + kvh) * T_SEQ * HD;

    const int r4 = lane >> 2;
    const int lrow = (lane & 7) + ((lane >> 3) & 1) * 8;

    // ---- preamble: Q-hi (temp, stage0 region) + Q-lo (persistent) ----
    #pragma unroll
    for (int j = 0; j < 8; j++) {
        int i = tid + j * 256;
        int row = i >> 4, cb = i & 15;
        uint32_t so = swz256(row, cb);
        size_t go = (qoff + (size_t)row * HD) * 2 + cb * 16;
        cp16(sb + ATT_ST0 + so, (const char*)qh + go);
        cp16(sb + ATT_QL  + so, (const char*)ql + go);
    }
    asm volatile("cp.async.commit_group;\n");
    asm volatile("cp.async.wait_group 0;\n");
    __syncthreads();

    uint32_t qhf[8][4];
    #pragma unroll
    for (int ks = 0; ks < 8; ks++) {
        int cb = 2 * ks + (lane >> 4);
        LDSM_X4(qhf[ks], sb + ATT_ST0 + swz256(16 * w + lrow, cb));
    }
    __syncthreads();

    auto load_stage = [&](int kt) {
        uint32_t st = sb + ATT_ST0 + (uint32_t)(kt % 3) * ATT_STAGE;
        size_t base = (koff + (size_t)kt * 64 * HD) * 2;
        #pragma unroll
        for (int j = 0; j < 4; j++) {
            int i = tid + j * 256;
            int row = i >> 4, cb = i & 15;
            uint32_t so = swz256(row, cb);
            size_t go = base + (size_t)row * 256 + cb * 16;
            cp16(st + ATT_KH + so, (const char*)kh + go);
            cp16(st + ATT_KL + so, (const char*)kl + go);
            cp16(st + ATT_VF + so, (const char*)vf + go);
        }
        asm volatile("cp.async.commit_group;\n");
    };

    const int nkt = 2 * (qt + 1);
    load_stage(0);
    load_stage(1);

    float acc[16][4];
    #pragma unroll
    for (int nt = 0; nt < 16; nt++)
        #pragma unroll
        for (int i = 0; i < 4; i++) acc[nt][i] = 0.f;
    float m0 = -1e30f, m1 = -1e30f, l0 = 0.f, l1 = 0.f;

    const int qrow0 = qt * 128 + 16 * w + r4;
    const int wmax  = qt * 128 + 16 * w + 15;

    for (int kt = 0; kt < nkt; kt++) {
        if (kt == nkt - 1) asm volatile("cp.async.wait_group 0;\n");
        else               asm volatile("cp.async.wait_group 1;\n");
        __syncthreads();
        if (kt + 2 < nkt) load_stage(kt + 2);

        int kvbase = kt * 64;
        if (kvbase > wmax) continue;
        uint32_t st = sb + ATT_ST0 + (uint32_t)(kt % 3) * ATT_STAGE;

        // ---- S = Q K^T (3-product) ----
        float sacc[8][4];
        #pragma unroll
        for (int nt = 0; nt < 8; nt++)
            #pragma unroll
            for (int i = 0; i < 4; i++) sacc[nt][i] = 0.f;

        #pragma unroll
        for (int ks = 0; ks < 8; ks++) {
            int cb = 2 * ks + (lane >> 4);
            uint32_t ql4[4];
            LDSM_X4(ql4, sb + ATT_QL + swz256(16 * w + lrow, cb));
            #pragma unroll
            for (int nt2 = 0; nt2 < 4; nt2++) {
                uint32_t bd = st + ATT_KH + swz256(16 * nt2 + lrow, cb);
                uint32_t kh4[4], kl4[4];
                LDSM_X4(kh4, bd);
                LDSM_X4(kl4, bd + (ATT_KL - ATT_KH));
                MMA16816(sacc[2*nt2],   qhf[ks], kh4[0], kh4[2]);
                MMA16816(sacc[2*nt2],   qhf[ks], kl4[0], kl4[2]);
                MMA16816(sacc[2*nt2],   ql4,     kh4[0], kh4[2]);
                MMA16816(sacc[2*nt2+1], qhf[ks], kh4[1], kh4[3]);
                MMA16816(sacc[2*nt2+1], qhf[ks], kl4[1], kl4[3]);
                MMA16816(sacc[2*nt2+1], ql4,     kh4[1], kh4[3]);
            }
        }

        // ---- causal mask ----
        if (kvbase + 63 > qrow0) {
            #pragma unroll
            for (int nt = 0; nt < 8; nt++) {
                int col = kvbase + 8 * nt + (lane & 3) * 2;
                if (col     > qrow0)     sacc[nt][0] = -1e30f;
                if (col + 1 > qrow0)     sacc[nt][1] = -1e30f;
                if (col     > qrow0 + 8) sacc[nt][2] = -1e30f;
                if (col + 1 > qrow0 + 8) sacc[nt][3] = -1e30f;
            }
        }

        // ---- online softmax ----
        float ml0 = -1e30f, ml1 = -1e30f;
        #pragma unroll
        for (int nt = 0; nt < 8; nt++) {
            ml0 = fmaxf(ml0, fmaxf(sacc[nt][0], sacc[nt][1]));
            ml1 = fmaxf(ml1, fmaxf(sacc[nt][2], sacc[nt][3]));
        }
        ml0 = fmaxf(ml0, __shfl_xor_sync(0xffffffffu, ml0, 1));
        ml0 = fmaxf(ml0, __shfl_xor_sync(0xffffffffu, ml0, 2));
        ml1 = fmaxf(ml1, __shfl_xor_sync(0xffffffffu, ml1, 1));
        ml1 = fmaxf(ml1, __shfl_xor_sync(0xffffffffu, ml1, 2));
        float mn0 = fmaxf(m0, ml0), mn1 = fmaxf(m1, ml1);
        float c0 = __expf(m0 - mn0), c1 = __expf(m1 - mn1);
        float ps0 = 0.f, ps1 = 0.f;
        #pragma unroll
        for (int nt = 0; nt < 8; nt++) {
            sacc[nt][0] = __expf(sacc[nt][0] - mn0);
            sacc[nt][1] = __expf(sacc[nt][1] - mn0);
            sacc[nt][2] = __expf(sacc[nt][2] - mn1);
            sacc[nt][3] = __expf(sacc[nt][3] - mn1);
            ps0 += sacc[nt][0] + sacc[nt][1];
            ps1 += sacc[nt][2] + sacc[nt][3];
        }
        ps0 += __shfl_xor_sync(0xffffffffu, ps0, 1);
        ps0 += __shfl_xor_sync(0xffffffffu, ps0, 2);
        ps1 += __shfl_xor_sync(0xffffffffu, ps1, 1);
        ps1 += __shfl_xor_sync(0xffffffffu, ps1, 2);
        l0 = l0 * c0 + ps0;
        l1 = l1 * c1 + ps1;
        m0 = mn0; m1 = mn1;
        #pragma unroll
        for (int nt = 0; nt < 16; nt++) {
            acc[nt][0] *= c0; acc[nt][1] *= c0;
            acc[nt][2] *= c1; acc[nt][3] *= c1;
        }

        // ---- pack P fragments (fp16 hi/lo) ----
        uint32_t ph[4][4], pl[4][4];
        #pragma unroll
        for (int j = 0; j < 4; j++) {
            #pragma unroll
            for (int half = 0; half < 2; half++) {
                float p0 = sacc[2*j+half][0], p1 = sacc[2*j+half][1];
                float p2 = sacc[2*j+half][2], p3 = sacc[2*j+half][3];
                __half h0 = __float2half_rn(p0), h1b = __float2half_rn(p1);
                __half h2 = __float2half_rn(p2), h3 = __float2half_rn(p3);
                ph[j][2*half]   = packh(__half2float(h0), __half2float(h1b));
                ph[j][2*half+1] = packh(__half2float(h2), __half2float(h3));
                pl[j][2*half]   = packh(p0 - __half2float(h0), p1 - __half2float(h1b));
                pl[j][2*half+1] = packh(p2 - __half2float(h2), p3 - __half2float(h3));
            }
        }

        // ---- O += P V (2-product: (ph+pl) * v_single) ----
        #pragma unroll
        for (int j = 0; j < 4; j++) {
            #pragma unroll
            for (int dt = 0; dt < 8; dt++) {
                int cb = 2 * dt + (lane >> 4);
                uint32_t v4[4];
                LDSM_X4_T(v4, st + ATT_VF + swz256(16 * j + lrow, cb));
                MMA16816(acc[2*dt],   ph[j], v4[0], v4[1]);
                MMA16816(acc[2*dt],   pl[j], v4[0], v4[1]);
                MMA16816(acc[2*dt+1], ph[j], v4[2], v4[3]);
                MMA16816(acc[2*dt+1], pl[j], v4[2], v4[3]);
            }
        }
    }

    // ---- epilogue: normalize, split to fp16 hi/lo, write [b*T+t][h*128+d] ----
    float i0 = 1.f / l0, i1 = 1.f / l1;
    const int trow0 = qt * 128 + 16 * w + r4;
    const size_t orow0 = (size_t)(b * T_SEQ + trow0) * 2048 + h * 128;
    const size_t orow1 = orow0 + 8 * 2048;
    #pragma unroll
    for (int nt = 0; nt < 16; nt++) {
        int d = 8 * nt + (lane & 3) * 2;
        float a0 = acc[nt][0] * i0, a1 = acc[nt][1] * i0;
        float a2 = acc[nt][2] * i1, a3 = acc[nt][3] * i1;
        __half h0 = __float2half_rn(a0), h1b = __float2half_rn(a1);
        __half h2 = __float2half_rn(a2), h3 = __float2half_rn(a3);
        *(uint32_t*)&oh[orow0 + d] = packh(__half2float(h0), __half2float(h1b));
        *(uint32_t*)&oh[orow1 + d] = packh(__half2float(h2), __half2float(h3));
        *(uint32_t*)&ol[orow0 + d] = packh(a0 - __half2float(h0), a1 - __half2float(h1b));
        *(uint32_t*)&ol[orow1 + d] = packh(a2 - __half2float(h2), a3 - __half2float(h3));
    }
}

// ---------------- launch ----------------
extern "C" void kernel_launch(void* const* d_in, const int* in_sizes, int n_in,
                              void* d_out, int out_size)
{
    const float* x   = (const float*)d_in[0];
    const float* w_q = (const float*)d_in[1];
    const float* w_k = (const float*)d_in[2];
    const float* w_v = (const float*)d_in[3];
    const float* w_o = (const float*)d_in[4];
    float* out = (float*)d_out;

    float *q, *k;
    __half *xF, *wF, *woF, *ah, *al;
    __half *qh, *ql, *kh, *kl, *vF;
    cudaGetSymbolAddress((void**)&q,   g_q);
    cudaGetSymbolAddress((void**)&k,   g_k);
    cudaGetSymbolAddress((void**)&xF,  g_xF);
    cudaGetSymbolAddress((void**)&wF,  g_wF);
    cudaGetSymbolAddress((void**)&woF, g_woF);
    cudaGetSymbolAddress((void**)&ah,  g_ah);
    cudaGetSymbolAddress((void**)&al,  g_al);
    cudaGetSymbolAddress((void**)&qh,  g_qh);
    cudaGetSymbolAddress((void**)&ql,  g_ql);
    cudaGetSymbolAddress((void**)&kh,  g_kh);
    cudaGetSymbolAddress((void**)&kl,  g_kl);
    cudaGetSymbolAddress((void**)&vF,  g_vF);

    // input conversions (all single fp16)
    {
        int n4;
        n4 = MROWS * KDIM / 4;
        convert_h<<<(n4 + 255) / 256, 256>>>(x, xF, n4);
        n4 = 2048 * KDIM / 4;
        convert_h<<<(n4 + 255) / 256, 256>>>(w_q, wF, n4);
        n4 = 512 * KDIM / 4;
        convert_h<<<(n4 + 255) / 256, 256>>>(w_k, wF + (size_t)2048 * KDIM, n4);
        convert_h<<<(n4 + 255) / 256, 256>>>(w_v, wF + (size_t)2560 * KDIM, n4);
        n4 = 2048 * KDIM / 4;
        convert_h<<<(n4 + 255) / 256, 256>>>(w_o, woF, n4);
    }

    cudaFuncSetAttribute(gemm_fp16<0,2>, cudaFuncAttributeMaxDynamicSharedMemorySize, GEMM_SMEM);
    cudaFuncSetAttribute(gemm_fp16<1,1>, cudaFuncAttributeMaxDynamicSharedMemorySize, GEMM_SMEM);

    // fused QKV projection, 1-product (q,k fp32; v direct fp16)
    gemm_fp16<1,1><<<dim3(3072 / 128, MROWS / 128), 256, GEMM_SMEM>>>(xF, xF, wF, q);

    // RoPE -> scaled fp16 hi/lo (scale folded into q)
    {
        long qp = (long)B_SZ * N_HEADS * T_SEQ * 64;
        long kp = (long)B_SZ * N_KV   * T_SEQ * 64;
        rope_split_h<<<(unsigned)((qp + 255) / 256), 256>>>(q, qh, ql, qp, 0.08838834764831845f);
        rope_split_h<<<(unsigned)((kp + 255) / 256), 256>>>(k, kh, kl, kp, 1.0f);
    }

    // tensor-core attention -> g_ah/g_al (fp16 hi/lo, [b*T+t][h*128+d])
    cudaFuncSetAttribute(attn_mma, cudaFuncAttributeMaxDynamicSharedMemorySize, ATT_SMEM);
    attn_mma<<<dim3(T_SEQ / 128, B_SZ * N_HEADS), 256, ATT_SMEM>>>(qh, ql, kh, kl, vF, ah, al);

    // O projection (2-product)
    gemm_fp16<0,2><<<dim3(2048 / 128, MROWS / 128), 256, GEMM_SMEM>>>(ah, al, woF, out);
}

// round 8
// speedup vs baseline: 1.9931x; 1.2442x over previous
#include <cuda_runtime.h>
#include <cuda_fp16.h>
#include <math.h>
#include <stdint.h>

#define B_SZ    2
#define T_SEQ   2048
#define D_MODEL 2048
#define N_HEADS 16
#define N_KV    4
#define HD      128
#define KDIM    2048
#define MROWS   (B_SZ * T_SEQ)          // 4096

// ---------------- scratch (static device globals; no allocs) ----------------
__device__ float g_q[(size_t)B_SZ * N_HEADS * T_SEQ * HD];
__device__ float g_k[(size_t)B_SZ * N_KV   * T_SEQ * HD];

__device__ __half g_xF[(size_t)MROWS * KDIM];   // x single fp16
__device__ __half g_wF[(size_t)3072 * KDIM];    // wq|wk|wv stacked, single fp16
__device__ __half g_woF[(size_t)2048 * KDIM];   // w_o single fp16
__device__ __half g_aF[(size_t)MROWS * KDIM];   // attention out single fp16

__device__ __half g_qh[(size_t)B_SZ * N_HEADS * T_SEQ * HD];
__device__ __half g_ql[(size_t)B_SZ * N_HEADS * T_SEQ * HD];
__device__ __half g_kh[(size_t)B_SZ * N_KV * T_SEQ * HD];
__device__ __half g_kl[(size_t)B_SZ * N_KV * T_SEQ * HD];
__device__ __half g_vF[(size_t)B_SZ * N_KV * T_SEQ * HD];   // v single fp16

// ---------------- helpers ----------------
__device__ __forceinline__ uint32_t smem_to_u32(const void* p) {
    uint32_t a;
    asm("{ .reg .u64 t; cvta.to.shared.u64 t, %1; cvt.u32.u64 %0, t; }" : "=r"(a) : "l"(p));
    return a;
}
#define SW128(off) ((off) ^ (((off) >> 3) & 0x70))

__device__ __forceinline__ void cp16(uint32_t saddr, const void* g) {
    asm volatile("cp.async.cg.shared.global [%0], [%1], 16;\n" :: "r"(saddr), "l"(g));
}
#define LDSM_X4(r, a) \
    asm volatile("ldmatrix.sync.aligned.m8n8.x4.shared.b16 {%0,%1,%2,%3}, [%4];" \
        : "=r"((r)[0]), "=r"((r)[1]), "=r"((r)[2]), "=r"((r)[3]) : "r"(a))
#define LDSM_X4_T(r, a) \
    asm volatile("ldmatrix.sync.aligned.m8n8.x4.trans.shared.b16 {%0,%1,%2,%3}, [%4];" \
        : "=r"((r)[0]), "=r"((r)[1]), "=r"((r)[2]), "=r"((r)[3]) : "r"(a))
#define MMA16816(c, a, b0, b1) \
    asm volatile("mma.sync.aligned.m16n8k16.row.col.f32.f16.f16.f32 " \
        "{%0,%1,%2,%3}, {%4,%5,%6,%7}, {%8,%9}, {%0,%1,%2,%3};" \
        : "+f"((c)[0]), "+f"((c)[1]), "+f"((c)[2]), "+f"((c)[3]) \
        : "r"((a)[0]), "r"((a)[1]), "r"((a)[2]), "r"((a)[3]), "r"(b0), "r"(b1))

__device__ __forceinline__ uint32_t packh(float a, float b) {
    __half2 t = __floats2half2_rn(a, b);
    return reinterpret_cast<uint32_t&>(t);
}

// ---------------- fp32 -> fp16 single ----------------
__global__ void convert_h(const float* __restrict__ src, __half* __restrict__ dst, int n4)
{
    int i = blockIdx.x * blockDim.x + threadIdx.x;
    if (i >= n4) return;
    float4 v = ((const float4*)src)[i];
    ((__half2*)dst)[2 * i]     = __floats2half2_rn(v.x, v.y);
    ((__half2*)dst)[2 * i + 1] = __floats2half2_rn(v.z, v.w);
}

// ---------------- fp16 GEMM: C = (A [+ Al]) @ B^T ----------------
// NPROD=1: A single. NPROD=2: A split hi/lo. B always single fp16.
// Tile 128x128, BK=64, 3-stage ring, 1 barrier per chunk.
// MODE 0: C row-major fp32.  MODE 1: QKV scatter (q,k fp32; v fp16 direct).
#define OFF_AH 0
#define OFF_AL 16384
#define OFF_B  32768
#define STAGE_BYTES 49152
#define GEMM_SMEM (3 * STAGE_BYTES)     // 147456

template<int MODE, int NPROD>
__global__ __launch_bounds__(256, 1)
void gemm_fp16(const __half* __restrict__ Ah, const __half* __restrict__ Al,
               const __half* __restrict__ Bf, float* __restrict__ C)
{
    extern __shared__ __align__(1024) char smem[];
    const uint32_t sb = smem_to_u32(smem);
    const int tid  = threadIdx.x;
    const int lane = tid & 31;
    const int wid  = tid >> 5;
    const int warp_m = (wid & 3) * 32;
    const int warp_n = (wid >> 2) * 64;
    const int bm0 = blockIdx.y * 128;
    const int bn0 = blockIdx.x * 128;

    float acc[2][8][4];
    #pragma unroll
    for (int mt = 0; mt < 2; mt++)
        #pragma unroll
        for (int nt = 0; nt < 8; nt++)
            #pragma unroll
            for (int i = 0; i < 4; i++) acc[mt][nt][i] = 0.f;

    auto load_chunk = [&](int c) {
        uint32_t st = sb + (uint32_t)(c % 3) * STAGE_BYTES;
        int k0 = c * 64;
        #pragma unroll
        for (int j = 0; j < 4; j++) {
            int i = tid + j * 256;
            int row = i >> 3, cb = (i & 7) * 16;
            uint32_t so = SW128((uint32_t)(row * 128 + cb));
            size_t goA = ((size_t)(bm0 + row) * KDIM + k0) * 2 + cb;
            size_t goB = ((size_t)(bn0 + row) * KDIM + k0) * 2 + cb;
            cp16(st + OFF_AH + so, (const char*)Ah + goA);
            if (NPROD == 2) cp16(st + OFF_AL + so, (const char*)Al + goA);
            cp16(st + OFF_B  + so, (const char*)Bf + goB);
        }
        asm volatile("cp.async.commit_group;\n");
    };

    load_chunk(0);
    load_chunk(1);

    const int NC = KDIM / 64;
    for (int c = 0; c < NC; c++) {
        if (c == NC - 1) asm volatile("cp.async.wait_group 0;\n");
        else             asm volatile("cp.async.wait_group 1;\n");
        __syncthreads();
        if (c + 2 < NC) load_chunk(c + 2);

        uint32_t st = sb + (uint32_t)(c % 3) * STAGE_BYTES;
        #pragma unroll
        for (int ks = 0; ks < 4; ks++) {
            uint32_t ah[2][4], al[2][4], bh[4][4];
            int lrow = (lane & 7) + ((lane >> 3) & 1) * 8;
            int lcb  = ks * 32 + (lane >> 4) * 16;
            #pragma unroll
            for (int mt = 0; mt < 2; mt++) {
                int arow = warp_m + mt * 16 + lrow;
                uint32_t ad = st + OFF_AH + SW128((uint32_t)(arow * 128 + lcb));
                LDSM_X4(ah[mt], ad);
                if (NPROD == 2) LDSM_X4(al[mt], ad + (OFF_AL - OFF_AH));
            }
            #pragma unroll
            for (int nt = 0; nt < 4; nt++) {
                int brow = warp_n + nt * 16 + lrow;
                LDSM_X4(bh[nt], st + OFF_B + SW128((uint32_t)(brow * 128 + lcb)));
            }
            #pragma unroll
            for (int mt = 0; mt < 2; mt++) {
                #pragma unroll
                for (int nt4 = 0; nt4 < 4; nt4++) {
                    MMA16816(acc[mt][2*nt4],   ah[mt], bh[nt4][0], bh[nt4][2]);
                    if (NPROD == 2) MMA16816(acc[mt][2*nt4], al[mt], bh[nt4][0], bh[nt4][2]);
                    MMA16816(acc[mt][2*nt4+1], ah[mt], bh[nt4][1], bh[nt4][3]);
                    if (NPROD == 2) MMA16816(acc[mt][2*nt4+1], al[mt], bh[nt4][1], bh[nt4][3]);
                }
            }
        }
    }

    const int rbase = bm0 + warp_m + (lane >> 2);
    const int cbase = bn0 + warp_n + (lane & 3) * 2;
    #pragma unroll
    for (int mt = 0; mt < 2; mt++) {
        #pragma unroll
        for (int hh = 0; hh < 2; hh++) {
            int row = rbase + mt * 16 + hh * 8;
            #pragma unroll
            for (int nt = 0; nt < 8; nt++) {
                int col = cbase + nt * 8;
                float2 v = make_float2(acc[mt][nt][2*hh], acc[mt][nt][2*hh+1]);
                if (MODE == 0) {
                    *(float2*)&C[(size_t)row * 2048 + col] = v;
                } else {
                    int b = row >> 11, tq = row & (T_SEQ - 1), d = col & 127;
                    if (col < 2048) {
                        int h = col >> 7;
                        float* base = g_q + (((size_t)(b * N_HEADS + h) * T_SEQ + tq) * HD + d);
                        *(float2*)base = v;
                    } else if (col < 2560) {
                        int h = (col - 2048) >> 7;
                        float* base = g_k + (((size_t)(b * N_KV + h) * T_SEQ + tq) * HD + d);
                        *(float2*)base = v;
                    } else {
                        int h = (col - 2560) >> 7;
                        size_t idx = ((size_t)(b * N_KV + h) * T_SEQ + tq) * HD + d;
                        *(uint32_t*)&g_vF[idx] = packh(v.x, v.y);
                    }
                }
            }
        }
    }
}

// ---------------- RoPE: fp32 in -> rotated, scaled fp16 hi/lo out ----------------
__global__ void rope_split_h(const float* __restrict__ src,
                             __half* __restrict__ hi,
                             __half* __restrict__ lo,
                             long total_pairs, float scale)
{
    long idx = (long)blockIdx.x * blockDim.x + threadIdx.x;
    if (idx >= total_pairs) return;
    int  i   = (int)(idx & 63);
    long row = idx >> 6;
    int  tpos = (int)(row & (T_SEQ - 1));
    const float* p = src + row * HD;
    float inv = __expf(-((float)i / 64.0f) * 13.815510557964274f);
    float s, c;
    sincosf((float)tpos * inv, &s, &c);
    float x1 = p[i], x2 = p[i + 64];
    float r1 = (x1 * c - x2 * s) * scale;
    float r2 = (x2 * c + x1 * s) * scale;
    __half h1 = __float2half_rn(r1), h2 = __float2half_rn(r2);
    hi[row * HD + i]      = h1;
    hi[row * HD + i + 64] = h2;
    lo[row * HD + i]      = __float2half_rn(r1 - __half2float(h1));
    lo[row * HD + i + 64] = __float2half_rn(r2 - __half2float(h2));
}

// ---------------- tensor-core flash attention ----------
// QK 3-product (q,k split hi/lo); PV 1-product (P,V single fp16).
#define ATT_QL    0
#define ATT_ST0   32768
#define ATT_STAGE 49152
#define ATT_KH 0
#define ATT_KL 16384
#define ATT_VF 32768
#define ATT_SMEM (ATT_ST0 + 3 * ATT_STAGE)   // 180224

__device__ __forceinline__ uint32_t swz256(int row, int cb) {
    return (uint32_t)(row * 256 + ((cb ^ (row & 7)) << 4));
}

__global__ __launch_bounds__(256, 1)
void attn_mma(const __half* __restrict__ qh, const __half* __restrict__ ql,
              const __half* __restrict__ kh, const __half* __restrict__ kl,
              const __half* __restrict__ vf,
              __half* __restrict__ oF)
{
    extern __shared__ __align__(1024) char smem[];
    const uint32_t sb = smem_to_u32(smem);
    const int tid  = threadIdx.x;
    const int w    = tid >> 5;
    const int lane = tid & 31;
    const int qt   = (gridDim.x - 1) - blockIdx.x;
    const int bh   = blockIdx.y;
    const int b    = bh >> 4;
    const int h    = bh & 15;
    const int kvh  = h >> 2;

    const size_t qoff = ((size_t)bh * T_SEQ + (size_t)qt * 128) * HD;
    const size_t koff = (size_t)(b * N_KV + kvh) * T_SEQ * HD;

    const int r4 = lane >> 2;
    const int lrow = (lane & 7) + ((lane >> 3) & 1) * 8;

    // ---- preamble: Q-hi (temp, stage0 region) + Q-lo (persistent) ----
    #pragma unroll
    for (int j = 0; j < 8; j++) {
        int i = tid + j * 256;
        int row = i >> 4, cb = i & 15;
        uint32_t so = swz256(row, cb);
        size_t go = (qoff + (size_t)row * HD) * 2 + cb * 16;
        cp16(sb + ATT_ST0 + so, (const char*)qh + go);
        cp16(sb + ATT_QL  + so, (const char*)ql + go);
    }
    asm volatile("cp.async.commit_group;\n");
    asm volatile("cp.async.wait_group 0;\n");
    __syncthreads();

    uint32_t qhf[8][4];
    #pragma unroll
    for (int ks = 0; ks < 8; ks++) {
        int cb = 2 * ks + (lane >> 4);
        LDSM_X4(qhf[ks], sb + ATT_ST0 + swz256(16 * w + lrow, cb));
    }
    __syncthreads();

    auto load_stage = [&](int kt) {
        uint32_t st = sb + ATT_ST0 + (uint32_t)(kt % 3) * ATT_STAGE;
        size_t base = (koff + (size_t)kt * 64 * HD) * 2;
        #pragma unroll
        for (int j = 0; j < 4; j++) {
            int i = tid + j * 256;
            int row = i >> 4, cb = i & 15;
            uint32_t so = swz256(row, cb);
            size_t go = base + (size_t)row * 256 + cb * 16;
            cp16(st + ATT_KH + so, (const char*)kh + go);
            cp16(st + ATT_KL + so, (const char*)kl + go);
            cp16(st + ATT_VF + so, (const char*)vf + go);
        }
        asm volatile("cp.async.commit_group;\n");
    };

    const int nkt = 2 * (qt + 1);
    load_stage(0);
    load_stage(1);

    float acc[16][4];
    #pragma unroll
    for (int nt = 0; nt < 16; nt++)
        #pragma unroll
        for (int i = 0; i < 4; i++) acc[nt][i] = 0.f;
    float m0 = -1e30f, m1 = -1e30f, l0 = 0.f, l1 = 0.f;

    const int qrow0 = qt * 128 + 16 * w + r4;
    const int wmax  = qt * 128 + 16 * w + 15;

    for (int kt = 0; kt < nkt; kt++) {
        if (kt == nkt - 1) asm volatile("cp.async.wait_group 0;\n");
        else               asm volatile("cp.async.wait_group 1;\n");
        __syncthreads();
        if (kt + 2 < nkt) load_stage(kt + 2);

        int kvbase = kt * 64;
        if (kvbase > wmax) continue;
        uint32_t st = sb + ATT_ST0 + (uint32_t)(kt % 3) * ATT_STAGE;

        // ---- S = Q K^T (3-product) ----
        float sacc[8][4];
        #pragma unroll
        for (int nt = 0; nt < 8; nt++)
            #pragma unroll
            for (int i = 0; i < 4; i++) sacc[nt][i] = 0.f;

        #pragma unroll
        for (int ks = 0; ks < 8; ks++) {
            int cb = 2 * ks + (lane >> 4);
            uint32_t ql4[4];
            LDSM_X4(ql4, sb + ATT_QL + swz256(16 * w + lrow, cb));
            #pragma unroll
            for (int nt2 = 0; nt2 < 4; nt2++) {
                uint32_t bd = st + ATT_KH + swz256(16 * nt2 + lrow, cb);
                uint32_t kh4[4], kl4[4];
                LDSM_X4(kh4, bd);
                LDSM_X4(kl4, bd + (ATT_KL - ATT_KH));
                MMA16816(sacc[2*nt2],   qhf[ks], kh4[0], kh4[2]);
                MMA16816(sacc[2*nt2],   qhf[ks], kl4[0], kl4[2]);
                MMA16816(sacc[2*nt2],   ql4,     kh4[0], kh4[2]);
                MMA16816(sacc[2*nt2+1], qhf[ks], kh4[1], kh4[3]);
                MMA16816(sacc[2*nt2+1], qhf[ks], kl4[1], kl4[3]);
                MMA16816(sacc[2*nt2+1], ql4,     kh4[1], kh4[3]);
            }
        }

        // ---- causal mask ----
        if (kvbase + 63 > qrow0) {
            #pragma unroll
            for (int nt = 0; nt < 8; nt++) {
                int col = kvbase + 8 * nt + (lane & 3) * 2;
                if (col     > qrow0)     sacc[nt][0] = -1e30f;
                if (col + 1 > qrow0)     sacc[nt][1] = -1e30f;
                if (col     > qrow0 + 8) sacc[nt][2] = -1e30f;
                if (col + 1 > qrow0 + 8) sacc[nt][3] = -1e30f;
            }
        }

        // ---- online softmax ----
        float ml0 = -1e30f, ml1 = -1e30f;
        #pragma unroll
        for (int nt = 0; nt < 8; nt++) {
            ml0 = fmaxf(ml0, fmaxf(sacc[nt][0], sacc[nt][1]));
            ml1 = fmaxf(ml1, fmaxf(sacc[nt][2], sacc[nt][3]));
        }
        ml0 = fmaxf(ml0, __shfl_xor_sync(0xffffffffu, ml0, 1));
        ml0 = fmaxf(ml0, __shfl_xor_sync(0xffffffffu, ml0, 2));
        ml1 = fmaxf(ml1, __shfl_xor_sync(0xffffffffu, ml1, 1));
        ml1 = fmaxf(ml1, __shfl_xor_sync(0xffffffffu, ml1, 2));
        float mn0 = fmaxf(m0, ml0), mn1 = fmaxf(m1, ml1);
        float c0 = __expf(m0 - mn0), c1 = __expf(m1 - mn1);
        float ps0 = 0.f, ps1 = 0.f;
        #pragma unroll
        for (int nt = 0; nt < 8; nt++) {
            sacc[nt][0] = __expf(sacc[nt][0] - mn0);
            sacc[nt][1] = __expf(sacc[nt][1] - mn0);
            sacc[nt][2] = __expf(sacc[nt][2] - mn1);
            sacc[nt][3] = __expf(sacc[nt][3] - mn1);
            ps0 += sacc[nt][0] + sacc[nt][1];
            ps1 += sacc[nt][2] + sacc[nt][3];
        }
        ps0 += __shfl_xor_sync(0xffffffffu, ps0, 1);
        ps0 += __shfl_xor_sync(0xffffffffu, ps0, 2);
        ps1 += __shfl_xor_sync(0xffffffffu, ps1, 1);
        ps1 += __shfl_xor_sync(0xffffffffu, ps1, 2);
        l0 = l0 * c0 + ps0;
        l1 = l1 * c1 + ps1;
        m0 = mn0; m1 = mn1;
        #pragma unroll
        for (int nt = 0; nt < 16; nt++) {
            acc[nt][0] *= c0; acc[nt][1] *= c0;
            acc[nt][2] *= c1; acc[nt][3] *= c1;
        }

        // ---- pack P fragments (single fp16) ----
        uint32_t ph[4][4];
        #pragma unroll
        for (int j = 0; j < 4; j++) {
            #pragma unroll
            for (int half = 0; half < 2; half++) {
                ph[j][2*half]   = packh(sacc[2*j+half][0], sacc[2*j+half][1]);
                ph[j][2*half+1] = packh(sacc[2*j+half][2], sacc[2*j+half][3]);
            }
        }

        // ---- O += P V (1-product) ----
        #pragma unroll
        for (int j = 0; j < 4; j++) {
            #pragma unroll
            for (int dt = 0; dt < 8; dt++) {
                int cb = 2 * dt + (lane >> 4);
                uint32_t v4[4];
                LDSM_X4_T(v4, st + ATT_VF + swz256(16 * j + lrow, cb));
                MMA16816(acc[2*dt],   ph[j], v4[0], v4[1]);
                MMA16816(acc[2*dt+1], ph[j], v4[2], v4[3]);
            }
        }
    }

    // ---- epilogue: normalize, write single fp16 [b*T+t][h*128+d] ----
    float i0 = 1.f / l0, i1 = 1.f / l1;
    const int trow0 = qt * 128 + 16 * w + r4;
    const size_t orow0 = (size_t)(b * T_SEQ + trow0) * 2048 + h * 128;
    const size_t orow1 = orow0 + 8 * 2048;
    #pragma unroll
    for (int nt = 0; nt < 16; nt++) {
        int d = 8 * nt + (lane & 3) * 2;
        *(uint32_t*)&oF[orow0 + d] = packh(acc[nt][0] * i0, acc[nt][1] * i0);
        *(uint32_t*)&oF[orow1 + d] = packh(acc[nt][2] * i1, acc[nt][3] * i1);
    }
}

// ---------------- launch ----------------
extern "C" void kernel_launch(void* const* d_in, const int* in_sizes, int n_in,
                              void* d_out, int out_size)
{
    const float* x   = (const float*)d_in[0];
    const float* w_q = (const float*)d_in[1];
    const float* w_k = (const float*)d_in[2];
    const float* w_v = (const float*)d_in[3];
    const float* w_o = (const float*)d_in[4];
    float* out = (float*)d_out;

    float *q, *k;
    __half *xF, *wF, *woF, *aF;
    __half *qh, *ql, *kh, *kl, *vF;
    cudaGetSymbolAddress((void**)&q,   g_q);
    cudaGetSymbolAddress((void**)&k,   g_k);
    cudaGetSymbolAddress((void**)&xF,  g_xF);
    cudaGetSymbolAddress((void**)&wF,  g_wF);
    cudaGetSymbolAddress((void**)&woF, g_woF);
    cudaGetSymbolAddress((void**)&aF,  g_aF);
    cudaGetSymbolAddress((void**)&qh,  g_qh);
    cudaGetSymbolAddress((void**)&ql,  g_ql);
    cudaGetSymbolAddress((void**)&kh,  g_kh);
    cudaGetSymbolAddress((void**)&kl,  g_kl);
    cudaGetSymbolAddress((void**)&vF,  g_vF);

    // input conversions (all single fp16)
    {
        int n4;
        n4 = MROWS * KDIM / 4;
        convert_h<<<(n4 + 255) / 256, 256>>>(x, xF, n4);
        n4 = 2048 * KDIM / 4;
        convert_h<<<(n4 + 255) / 256, 256>>>(w_q, wF, n4);
        n4 = 512 * KDIM / 4;
        convert_h<<<(n4 + 255) / 256, 256>>>(w_k, wF + (size_t)2048 * KDIM, n4);
        convert_h<<<(n4 + 255) / 256, 256>>>(w_v, wF + (size_t)2560 * KDIM, n4);
        n4 = 2048 * KDIM / 4;
        convert_h<<<(n4 + 255) / 256, 256>>>(w_o, woF, n4);
    }

    cudaFuncSetAttribute(gemm_fp16<0,1>, cudaFuncAttributeMaxDynamicSharedMemorySize, GEMM_SMEM);
    cudaFuncSetAttribute(gemm_fp16<1,1>, cudaFuncAttributeMaxDynamicSharedMemorySize, GEMM_SMEM);

    // fused QKV projection, 1-product (q,k fp32; v direct fp16)
    gemm_fp16<1,1><<<dim3(3072 / 128, MROWS / 128), 256, GEMM_SMEM>>>(xF, xF, wF, q);

    // RoPE -> scaled fp16 hi/lo (scale folded into q)
    {
        long qp = (long)B_SZ * N_HEADS * T_SEQ * 64;
        long kp = (long)B_SZ * N_KV   * T_SEQ * 64;
        rope_split_h<<<(unsigned)((qp + 255) / 256), 256>>>(q, qh, ql, qp, 0.08838834764831845f);
        rope_split_h<<<(unsigned)((kp + 255) / 256), 256>>>(k, kh, kl, kp, 1.0f);
    }

    // tensor-core attention -> g_aF (single fp16, [b*T+t][h*128+d])
    cudaFuncSetAttribute(attn_mma, cudaFuncAttributeMaxDynamicSharedMemorySize, ATT_SMEM);
    attn_mma<<<dim3(T_SEQ / 128, B_SZ * N_HEADS), 256, ATT_SMEM>>>(qh, ql, kh, kl, vF, aF);

    // O projection (1-product)
    gemm_fp16<0,1><<<dim3(2048 / 128, MROWS / 128), 256, GEMM_SMEM>>>(aF, aF, woF, out);
}

// round 9
// speedup vs baseline: 2.3584x; 1.1833x over previous
#include <cuda_runtime.h>
#include <cuda_fp16.h>
#include <math.h>
#include <stdint.h>

#define B_SZ    2
#define T_SEQ   2048
#define D_MODEL 2048
#define N_HEADS 16
#define N_KV    4
#define HD      128
#define KDIM    2048
#define MROWS   (B_SZ * T_SEQ)          // 4096

// ---------------- scratch (static device globals; no allocs) ----------------
__device__ float g_q[(size_t)B_SZ * N_HEADS * T_SEQ * HD];
__device__ float g_k[(size_t)B_SZ * N_KV   * T_SEQ * HD];

__device__ __half g_xF[(size_t)MROWS * KDIM];   // x single fp16
__device__ __half g_wF[(size_t)3072 * KDIM];    // wq|wk|wv stacked, single fp16
__device__ __half g_woF[(size_t)2048 * KDIM];   // w_o single fp16
__device__ __half g_aF[(size_t)MROWS * KDIM];   // attention out single fp16

__device__ __half g_qF[(size_t)B_SZ * N_HEADS * T_SEQ * HD];
__device__ __half g_kF[(size_t)B_SZ * N_KV * T_SEQ * HD];
__device__ __half g_vF[(size_t)B_SZ * N_KV * T_SEQ * HD];

// ---------------- helpers ----------------
__device__ __forceinline__ uint32_t smem_to_u32(const void* p) {
    uint32_t a;
    asm("{ .reg .u64 t; cvta.to.shared.u64 t, %1; cvt.u32.u64 %0, t; }" : "=r"(a) : "l"(p));
    return a;
}
#define SW128(off) ((off) ^ (((off) >> 3) & 0x70))

__device__ __forceinline__ void cp16(uint32_t saddr, const void* g) {
    asm volatile("cp.async.cg.shared.global [%0], [%1], 16;\n" :: "r"(saddr), "l"(g));
}
#define LDSM_X4(r, a) \
    asm volatile("ldmatrix.sync.aligned.m8n8.x4.shared.b16 {%0,%1,%2,%3}, [%4];" \
        : "=r"((r)[0]), "=r"((r)[1]), "=r"((r)[2]), "=r"((r)[3]) : "r"(a))
#define LDSM_X4_T(r, a) \
    asm volatile("ldmatrix.sync.aligned.m8n8.x4.trans.shared.b16 {%0,%1,%2,%3}, [%4];" \
        : "=r"((r)[0]), "=r"((r)[1]), "=r"((r)[2]), "=r"((r)[3]) : "r"(a))
#define MMA16816(c, a, b0, b1) \
    asm volatile("mma.sync.aligned.m16n8k16.row.col.f32.f16.f16.f32 " \
        "{%0,%1,%2,%3}, {%4,%5,%6,%7}, {%8,%9}, {%0,%1,%2,%3};" \
        : "+f"((c)[0]), "+f"((c)[1]), "+f"((c)[2]), "+f"((c)[3]) \
        : "r"((a)[0]), "r"((a)[1]), "r"((a)[2]), "r"((a)[3]), "r"(b0), "r"(b1))

__device__ __forceinline__ uint32_t packh(float a, float b) {
    __half2 t = __floats2half2_rn(a, b);
    return reinterpret_cast<uint32_t&>(t);
}

// ---------------- fp32 -> fp16 single ----------------
__global__ void convert_h(const float* __restrict__ src, __half* __restrict__ dst, int n4)
{
    int i = blockIdx.x * blockDim.x + threadIdx.x;
    if (i >= n4) return;
    float4 v = ((const float4*)src)[i];
    ((__half2*)dst)[2 * i]     = __floats2half2_rn(v.x, v.y);
    ((__half2*)dst)[2 * i + 1] = __floats2half2_rn(v.z, v.w);
}

// ---------------- fp16 GEMM: C = A @ B^T (all single fp16) ----------------
// Tile 128x128, BK=64, 3-stage ring, 1 barrier per chunk.
// MODE 0: C row-major fp32.  MODE 1: QKV scatter (q,k fp32; v fp16 direct).
#define OFF_A  0
#define OFF_B  16384
#define STAGE_BYTES 32768
#define GEMM_SMEM (3 * STAGE_BYTES)     // 98304

template<int MODE>
__global__ __launch_bounds__(256, 1)
void gemm_fp16(const __half* __restrict__ Af, const __half* __restrict__ Bf,
               float* __restrict__ C)
{
    extern __shared__ __align__(1024) char smem[];
    const uint32_t sb = smem_to_u32(smem);
    const int tid  = threadIdx.x;
    const int lane = tid & 31;
    const int wid  = tid >> 5;
    const int warp_m = (wid & 3) * 32;
    const int warp_n = (wid >> 2) * 64;
    const int bm0 = blockIdx.y * 128;
    const int bn0 = blockIdx.x * 128;

    float acc[2][8][4];
    #pragma unroll
    for (int mt = 0; mt < 2; mt++)
        #pragma unroll
        for (int nt = 0; nt < 8; nt++)
            #pragma unroll
            for (int i = 0; i < 4; i++) acc[mt][nt][i] = 0.f;

    auto load_chunk = [&](int c) {
        uint32_t st = sb + (uint32_t)(c % 3) * STAGE_BYTES;
        int k0 = c * 64;
        #pragma unroll
        for (int j = 0; j < 4; j++) {
            int i = tid + j * 256;
            int row = i >> 3, cb = (i & 7) * 16;
            uint32_t so = SW128((uint32_t)(row * 128 + cb));
            size_t goA = ((size_t)(bm0 + row) * KDIM + k0) * 2 + cb;
            size_t goB = ((size_t)(bn0 + row) * KDIM + k0) * 2 + cb;
            cp16(st + OFF_A + so, (const char*)Af + goA);
            cp16(st + OFF_B + so, (const char*)Bf + goB);
        }
        asm volatile("cp.async.commit_group;\n");
    };

    load_chunk(0);
    load_chunk(1);

    const int NC = KDIM / 64;
    for (int c = 0; c < NC; c++) {
        if (c == NC - 1) asm volatile("cp.async.wait_group 0;\n");
        else             asm volatile("cp.async.wait_group 1;\n");
        __syncthreads();
        if (c + 2 < NC) load_chunk(c + 2);

        uint32_t st = sb + (uint32_t)(c % 3) * STAGE_BYTES;
        #pragma unroll
        for (int ks = 0; ks < 4; ks++) {
            uint32_t ah[2][4], bh[4][4];
            int lrow = (lane & 7) + ((lane >> 3) & 1) * 8;
            int lcb  = ks * 32 + (lane >> 4) * 16;
            #pragma unroll
            for (int mt = 0; mt < 2; mt++) {
                int arow = warp_m + mt * 16 + lrow;
                LDSM_X4(ah[mt], st + OFF_A + SW128((uint32_t)(arow * 128 + lcb)));
            }
            #pragma unroll
            for (int nt = 0; nt < 4; nt++) {
                int brow = warp_n + nt * 16 + lrow;
                LDSM_X4(bh[nt], st + OFF_B + SW128((uint32_t)(brow * 128 + lcb)));
            }
            #pragma unroll
            for (int mt = 0; mt < 2; mt++) {
                #pragma unroll
                for (int nt4 = 0; nt4 < 4; nt4++) {
                    MMA16816(acc[mt][2*nt4],   ah[mt], bh[nt4][0], bh[nt4][2]);
                    MMA16816(acc[mt][2*nt4+1], ah[mt], bh[nt4][1], bh[nt4][3]);
                }
            }
        }
    }

    const int rbase = bm0 + warp_m + (lane >> 2);
    const int cbase = bn0 + warp_n + (lane & 3) * 2;
    #pragma unroll
    for (int mt = 0; mt < 2; mt++) {
        #pragma unroll
        for (int hh = 0; hh < 2; hh++) {
            int row = rbase + mt * 16 + hh * 8;
            #pragma unroll
            for (int nt = 0; nt < 8; nt++) {
                int col = cbase + nt * 8;
                float2 v = make_float2(acc[mt][nt][2*hh], acc[mt][nt][2*hh+1]);
                if (MODE == 0) {
                    *(float2*)&C[(size_t)row * 2048 + col] = v;
                } else {
                    int b = row >> 11, tq = row & (T_SEQ - 1), d = col & 127;
                    if (col < 2048) {
                        int h = col >> 7;
                        float* base = g_q + (((size_t)(b * N_HEADS + h) * T_SEQ + tq) * HD + d);
                        *(float2*)base = v;
                    } else if (col < 2560) {
                        int h = (col - 2048) >> 7;
                        float* base = g_k + (((size_t)(b * N_KV + h) * T_SEQ + tq) * HD + d);
                        *(float2*)base = v;
                    } else {
                        int h = (col - 2560) >> 7;
                        size_t idx = ((size_t)(b * N_KV + h) * T_SEQ + tq) * HD + d;
                        *(uint32_t*)&g_vF[idx] = packh(v.x, v.y);
                    }
                }
            }
        }
    }
}

// ---------------- RoPE: fp32 in -> rotated, scaled single fp16 out ----------------
__global__ void rope_single_h(const float* __restrict__ src,
                              __half* __restrict__ dst,
                              long total_pairs, float scale)
{
    long idx = (long)blockIdx.x * blockDim.x + threadIdx.x;
    if (idx >= total_pairs) return;
    int  i   = (int)(idx & 63);
    long row = idx >> 6;
    int  tpos = (int)(row & (T_SEQ - 1));
    const float* p = src + row * HD;
    float inv = __expf(-((float)i / 64.0f) * 13.815510557964274f);
    float s, c;
    sincosf((float)tpos * inv, &s, &c);
    float x1 = p[i], x2 = p[i + 64];
    dst[row * HD + i]      = __float2half_rn((x1 * c - x2 * s) * scale);
    dst[row * HD + i + 64] = __float2half_rn((x2 * c + x1 * s) * scale);
}

// ---------------- tensor-core flash attention (all single fp16) ----------
// BM=128 q-rows, 8 warps x 16 rows, BN=64 kv per stage, 3-stage K+V ring.
// Q entirely in registers.
#define ATT_K 0
#define ATT_V 16384
#define ATT_STAGE 32768
#define ATT_SMEM (3 * ATT_STAGE)   // 98304

__device__ __forceinline__ uint32_t swz256(int row, int cb) {
    return (uint32_t)(row * 256 + ((cb ^ (row & 7)) << 4));
}

__global__ __launch_bounds__(256, 1)
void attn_mma(const __half* __restrict__ qf, const __half* __restrict__ kf,
              const __half* __restrict__ vf, __half* __restrict__ oF)
{
    extern __shared__ __align__(1024) char smem[];
    const uint32_t sb = smem_to_u32(smem);
    const int tid  = threadIdx.x;
    const int w    = tid >> 5;
    const int lane = tid & 31;
    const int qt   = (gridDim.x - 1) - blockIdx.x;
    const int bh   = blockIdx.y;
    const int b    = bh >> 4;
    const int h    = bh & 15;
    const int kvh  = h >> 2;

    const size_t qoff = ((size_t)bh * T_SEQ + (size_t)qt * 128) * HD;
    const size_t koff = (size_t)(b * N_KV + kvh) * T_SEQ * HD;

    const int r4 = lane >> 2;
    const int lrow = (lane & 7) + ((lane >> 3) & 1) * 8;

    // ---- preamble: stage Q in stage-0 region, pull to registers ----
    #pragma unroll
    for (int j = 0; j < 8; j++) {
        int i = tid + j * 256;
        int row = i >> 4, cb = i & 15;
        uint32_t so = swz256(row, cb);
        cp16(sb + so, (const char*)qf + (qoff + (size_t)row * HD) * 2 + cb * 16);
    }
    asm volatile("cp.async.commit_group;\n");
    asm volatile("cp.async.wait_group 0;\n");
    __syncthreads();

    uint32_t qr[8][4];
    #pragma unroll
    for (int ks = 0; ks < 8; ks++) {
        int cb = 2 * ks + (lane >> 4);
        LDSM_X4(qr[ks], sb + swz256(16 * w + lrow, cb));
    }
    __syncthreads();   // all reads done before KV stage 0 overwrites

    auto load_stage = [&](int kt) {
        uint32_t st = sb + (uint32_t)(kt % 3) * ATT_STAGE;
        size_t base = (koff + (size_t)kt * 64 * HD) * 2;
        #pragma unroll
        for (int j = 0; j < 4; j++) {
            int i = tid + j * 256;
            int row = i >> 4, cb = i & 15;
            uint32_t so = swz256(row, cb);
            size_t go = base + (size_t)row * 256 + cb * 16;
            cp16(st + ATT_K + so, (const char*)kf + go);
            cp16(st + ATT_V + so, (const char*)vf + go);
        }
        asm volatile("cp.async.commit_group;\n");
    };

    const int nkt = 2 * (qt + 1);
    load_stage(0);
    load_stage(1);

    float acc[16][4];
    #pragma unroll
    for (int nt = 0; nt < 16; nt++)
        #pragma unroll
        for (int i = 0; i < 4; i++) acc[nt][i] = 0.f;
    float m0 = -1e30f, m1 = -1e30f, l0 = 0.f, l1 = 0.f;

    const int qrow0 = qt * 128 + 16 * w + r4;
    const int wmax  = qt * 128 + 16 * w + 15;

    for (int kt = 0; kt < nkt; kt++) {
        if (kt == nkt - 1) asm volatile("cp.async.wait_group 0;\n");
        else               asm volatile("cp.async.wait_group 1;\n");
        __syncthreads();
        if (kt + 2 < nkt) load_stage(kt + 2);

        int kvbase = kt * 64;
        if (kvbase > wmax) continue;
        uint32_t st = sb + (uint32_t)(kt % 3) * ATT_STAGE;

        // ---- S = Q K^T (single product) ----
        float sacc[8][4];
        #pragma unroll
        for (int nt = 0; nt < 8; nt++)
            #pragma unroll
            for (int i = 0; i < 4; i++) sacc[nt][i] = 0.f;

        #pragma unroll
        for (int ks = 0; ks < 8; ks++) {
            int cb = 2 * ks + (lane >> 4);
            #pragma unroll
            for (int nt2 = 0; nt2 < 4; nt2++) {
                uint32_t k4[4];
                LDSM_X4(k4, st + ATT_K + swz256(16 * nt2 + lrow, cb));
                MMA16816(sacc[2*nt2],   qr[ks], k4[0], k4[2]);
                MMA16816(sacc[2*nt2+1], qr[ks], k4[1], k4[3]);
            }
        }

        // ---- causal mask (scale folded into q) ----
        if (kvbase + 63 > qrow0) {
            #pragma unroll
            for (int nt = 0; nt < 8; nt++) {
                int col = kvbase + 8 * nt + (lane & 3) * 2;
                if (col     > qrow0)     sacc[nt][0] = -1e30f;
                if (col + 1 > qrow0)     sacc[nt][1] = -1e30f;
                if (col     > qrow0 + 8) sacc[nt][2] = -1e30f;
                if (col + 1 > qrow0 + 8) sacc[nt][3] = -1e30f;
            }
        }

        // ---- online softmax ----
        float ml0 = -1e30f, ml1 = -1e30f;
        #pragma unroll
        for (int nt = 0; nt < 8; nt++) {
            ml0 = fmaxf(ml0, fmaxf(sacc[nt][0], sacc[nt][1]));
            ml1 = fmaxf(ml1, fmaxf(sacc[nt][2], sacc[nt][3]));
        }
        ml0 = fmaxf(ml0, __shfl_xor_sync(0xffffffffu, ml0, 1));
        ml0 = fmaxf(ml0, __shfl_xor_sync(0xffffffffu, ml0, 2));
        ml1 = fmaxf(ml1, __shfl_xor_sync(0xffffffffu, ml1, 1));
        ml1 = fmaxf(ml1, __shfl_xor_sync(0xffffffffu, ml1, 2));
        float mn0 = fmaxf(m0, ml0), mn1 = fmaxf(m1, ml1);
        float c0 = __expf(m0 - mn0), c1 = __expf(m1 - mn1);
        float ps0 = 0.f, ps1 = 0.f;
        #pragma unroll
        for (int nt = 0; nt < 8; nt++) {
            sacc[nt][0] = __expf(sacc[nt][0] - mn0);
            sacc[nt][1] = __expf(sacc[nt][1] - mn0);
            sacc[nt][2] = __expf(sacc[nt][2] - mn1);
            sacc[nt][3] = __expf(sacc[nt][3] - mn1);
            ps0 += sacc[nt][0] + sacc[nt][1];
            ps1 += sacc[nt][2] + sacc[nt][3];
        }
        ps0 += __shfl_xor_sync(0xffffffffu, ps0, 1);
        ps0 += __shfl_xor_sync(0xffffffffu, ps0, 2);
        ps1 += __shfl_xor_sync(0xffffffffu, ps1, 1);
        ps1 += __shfl_xor_sync(0xffffffffu, ps1, 2);
        l0 = l0 * c0 + ps0;
        l1 = l1 * c1 + ps1;
        m0 = mn0; m1 = mn1;
        #pragma unroll
        for (int nt = 0; nt < 16; nt++) {
            acc[nt][0] *= c0; acc[nt][1] *= c0;
            acc[nt][2] *= c1; acc[nt][3] *= c1;
        }

        // ---- pack P fragments (single fp16) ----
        uint32_t ph[4][4];
        #pragma unroll
        for (int j = 0; j < 4; j++) {
            #pragma unroll
            for (int half = 0; half < 2; half++) {
                ph[j][2*half]   = packh(sacc[2*j+half][0], sacc[2*j+half][1]);
                ph[j][2*half+1] = packh(sacc[2*j+half][2], sacc[2*j+half][3]);
            }
        }

        // ---- O += P V (single product) ----
        #pragma unroll
        for (int j = 0; j < 4; j++) {
            #pragma unroll
            for (int dt = 0; dt < 8; dt++) {
                int cb = 2 * dt + (lane >> 4);
                uint32_t v4[4];
                LDSM_X4_T(v4, st + ATT_V + swz256(16 * j + lrow, cb));
                MMA16816(acc[2*dt],   ph[j], v4[0], v4[1]);
                MMA16816(acc[2*dt+1], ph[j], v4[2], v4[3]);
            }
        }
    }

    // ---- epilogue: normalize, write single fp16 [b*T+t][h*128+d] ----
    float i0 = 1.f / l0, i1 = 1.f / l1;
    const int trow0 = qt * 128 + 16 * w + r4;
    const size_t orow0 = (size_t)(b * T_SEQ + trow0) * 2048 + h * 128;
    const size_t orow1 = orow0 + 8 * 2048;
    #pragma unroll
    for (int nt = 0; nt < 16; nt++) {
        int d = 8 * nt + (lane & 3) * 2;
        *(uint32_t*)&oF[orow0 + d] = packh(acc[nt][0] * i0, acc[nt][1] * i0);
        *(uint32_t*)&oF[orow1 + d] = packh(acc[nt][2] * i1, acc[nt][3] * i1);
    }
}

// ---------------- launch ----------------
extern "C" void kernel_launch(void* const* d_in, const int* in_sizes, int n_in,
                              void* d_out, int out_size)
{
    const float* x   = (const float*)d_in[0];
    const float* w_q = (const float*)d_in[1];
    const float* w_k = (const float*)d_in[2];
    const float* w_v = (const float*)d_in[3];
    const float* w_o = (const float*)d_in[4];
    float* out = (float*)d_out;

    float *q, *k;
    __half *xF, *wF, *woF, *aF, *qF, *kF, *vF;
    cudaGetSymbolAddress((void**)&q,   g_q);
    cudaGetSymbolAddress((void**)&k,   g_k);
    cudaGetSymbolAddress((void**)&xF,  g_xF);
    cudaGetSymbolAddress((void**)&wF,  g_wF);
    cudaGetSymbolAddress((void**)&woF, g_woF);
    cudaGetSymbolAddress((void**)&aF,  g_aF);
    cudaGetSymbolAddress((void**)&qF,  g_qF);
    cudaGetSymbolAddress((void**)&kF,  g_kF);
    cudaGetSymbolAddress((void**)&vF,  g_vF);

    // input conversions (all single fp16)
    {
        int n4;
        n4 = MROWS * KDIM / 4;
        convert_h<<<(n4 + 255) / 256, 256>>>(x, xF, n4);
        n4 = 2048 * KDIM / 4;
        convert_h<<<(n4 + 255) / 256, 256>>>(w_q, wF, n4);
        n4 = 512 * KDIM / 4;
        convert_h<<<(n4 + 255) / 256, 256>>>(w_k, wF + (size_t)2048 * KDIM, n4);
        convert_h<<<(n4 + 255) / 256, 256>>>(w_v, wF + (size_t)2560 * KDIM, n4);
        n4 = 2048 * KDIM / 4;
        convert_h<<<(n4 + 255) / 256, 256>>>(w_o, woF, n4);
    }

    cudaFuncSetAttribute(gemm_fp16<0>, cudaFuncAttributeMaxDynamicSharedMemorySize, GEMM_SMEM);
    cudaFuncSetAttribute(gemm_fp16<1>, cudaFuncAttributeMaxDynamicSharedMemorySize, GEMM_SMEM);

    // fused QKV projection (q,k fp32; v direct fp16)
    gemm_fp16<1><<<dim3(3072 / 128, MROWS / 128), 256, GEMM_SMEM>>>(xF, wF, q);

    // RoPE -> single fp16 (scale folded into q)
    {
        long qp = (long)B_SZ * N_HEADS * T_SEQ * 64;
        long kp = (long)B_SZ * N_KV   * T_SEQ * 64;
        rope_single_h<<<(unsigned)((qp + 255) / 256), 256>>>(q, qF, qp, 0.08838834764831845f);
        rope_single_h<<<(unsigned)((kp + 255) / 256), 256>>>(k, kF, kp, 1.0f);
    }

    // tensor-core attention -> g_aF (single fp16, [b*T+t][h*128+d])
    cudaFuncSetAttribute(attn_mma, cudaFuncAttributeMaxDynamicSharedMemorySize, ATT_SMEM);
    attn_mma<<<dim3(T_SEQ / 128, B_SZ * N_HEADS), 256, ATT_SMEM>>>(qF, kF, vF, aF);

    // O projection
    gemm_fp16<0><<<dim3(2048 / 128, MROWS / 128), 256, GEMM_SMEM>>>(aF, woF, out);
}

// round 10
// speedup vs baseline: 2.5583x; 1.0848x over previous
#include <cuda_runtime.h>
#include <cuda_fp16.h>
#include <math.h>
#include <stdint.h>

#define B_SZ    2
#define T_SEQ   2048
#define D_MODEL 2048
#define N_HEADS 16
#define N_KV    4
#define HD      128
#define KDIM    2048
#define MROWS   (B_SZ * T_SEQ)          // 4096

// ---------------- scratch (static device globals; no allocs) ----------------
__device__ float g_q[(size_t)B_SZ * N_HEADS * T_SEQ * HD];
__device__ float g_k[(size_t)B_SZ * N_KV   * T_SEQ * HD];

__device__ __half g_xF[(size_t)MROWS * KDIM];
__device__ __half g_wF[(size_t)3072 * KDIM];    // wq|wk|wv stacked
__device__ __half g_woF[(size_t)2048 * KDIM];
__device__ __half g_aF[(size_t)MROWS * KDIM];

__device__ __half g_qF[(size_t)B_SZ * N_HEADS * T_SEQ * HD];
__device__ __half g_kF[(size_t)B_SZ * N_KV * T_SEQ * HD];
__device__ __half g_vF[(size_t)B_SZ * N_KV * T_SEQ * HD];

// ---------------- helpers ----------------
__device__ __forceinline__ uint32_t smem_to_u32(const void* p) {
    uint32_t a;
    asm("{ .reg .u64 t; cvta.to.shared.u64 t, %1; cvt.u32.u64 %0, t; }" : "=r"(a) : "l"(p));
    return a;
}
#define SW128(off) ((off) ^ (((off) >> 3) & 0x70))

__device__ __forceinline__ void cp16(uint32_t saddr, const void* g) {
    asm volatile("cp.async.cg.shared.global [%0], [%1], 16;\n" :: "r"(saddr), "l"(g));
}
#define LDSM_X4(r, a) \
    asm volatile("ldmatrix.sync.aligned.m8n8.x4.shared.b16 {%0,%1,%2,%3}, [%4];" \
        : "=r"((r)[0]), "=r"((r)[1]), "=r"((r)[2]), "=r"((r)[3]) : "r"(a))
#define LDSM_X4_T(r, a) \
    asm volatile("ldmatrix.sync.aligned.m8n8.x4.trans.shared.b16 {%0,%1,%2,%3}, [%4];" \
        : "=r"((r)[0]), "=r"((r)[1]), "=r"((r)[2]), "=r"((r)[3]) : "r"(a))
#define MMA16816(c, a, b0, b1) \
    asm volatile("mma.sync.aligned.m16n8k16.row.col.f32.f16.f16.f32 " \
        "{%0,%1,%2,%3}, {%4,%5,%6,%7}, {%8,%9}, {%0,%1,%2,%3};" \
        : "+f"((c)[0]), "+f"((c)[1]), "+f"((c)[2]), "+f"((c)[3]) \
        : "r"((a)[0]), "r"((a)[1]), "r"((a)[2]), "r"((a)[3]), "r"(b0), "r"(b1))

__device__ __forceinline__ uint32_t packh(float a, float b) {
    __half2 t = __floats2half2_rn(a, b);
    return reinterpret_cast<uint32_t&>(t);
}

// ---------------- fused fp32 -> fp16 conversion of all inputs ----------------
#define CV_X   2097152                       // float4 counts
#define CV_WQ  (CV_X  + 1048576)
#define CV_WK  (CV_WQ + 262144)
#define CV_WV  (CV_WK + 262144)
#define CV_WO  (CV_WV + 1048576)             // 4718592 total

__global__ void convert_all(const float* __restrict__ x,  const float* __restrict__ wq,
                            const float* __restrict__ wk, const float* __restrict__ wv,
                            const float* __restrict__ wo,
                            __half* __restrict__ xF, __half* __restrict__ wF,
                            __half* __restrict__ woF)
{
    int i = blockIdx.x * blockDim.x + threadIdx.x;
    if (i >= CV_WO) return;
    const float* src; __half* dst; int off;
    if      (i < CV_X)  { src = x;  dst = xF;  off = i; }
    else if (i < CV_WQ) { src = wq; dst = wF;  off = i - CV_X; }
    else if (i < CV_WK) { src = wk; dst = wF + (size_t)2048 * KDIM; off = i - CV_WQ; }
    else if (i < CV_WV) { src = wv; dst = wF + (size_t)2560 * KDIM; off = i - CV_WK; }
    else                { src = wo; dst = woF; off = i - CV_WV; }
    float4 v = ((const float4*)src)[off];
    ((__half2*)dst)[2 * off]     = __floats2half2_rn(v.x, v.y);
    ((__half2*)dst)[2 * off + 1] = __floats2half2_rn(v.z, v.w);
}

// ---------------- fp16 GEMM: C = A @ B^T, tile 256(M) x 128(N) ----------------
// 8 warps, each 64x64. BK=64, 3-stage ring, 1 barrier per chunk.
// MODE 0: C row-major fp32. MODE 1: QKV scatter (q,k fp32; v fp16 direct).
#define OFF_A  0
#define OFF_B  32768
#define STAGE_BYTES 49152
#define GEMM_SMEM (3 * STAGE_BYTES)     // 147456

template<int MODE>
__global__ __launch_bounds__(256, 1)
void gemm_fp16(const __half* __restrict__ Af, const __half* __restrict__ Bf,
               float* __restrict__ C)
{
    extern __shared__ __align__(1024) char smem[];
    const uint32_t sb = smem_to_u32(smem);
    const int tid  = threadIdx.x;
    const int lane = tid & 31;
    const int wid  = tid >> 5;
    const int warp_m = (wid & 3) * 64;
    const int warp_n = (wid >> 2) * 64;
    const int bm0 = blockIdx.y * 256;
    const int bn0 = blockIdx.x * 128;

    float acc[4][8][4];
    #pragma unroll
    for (int mt = 0; mt < 4; mt++)
        #pragma unroll
        for (int nt = 0; nt < 8; nt++)
            #pragma unroll
            for (int i = 0; i < 4; i++) acc[mt][nt][i] = 0.f;

    auto load_chunk = [&](int c) {
        uint32_t st = sb + (uint32_t)(c % 3) * STAGE_BYTES;
        int k0 = c * 64;
        #pragma unroll
        for (int j = 0; j < 8; j++) {              // A: 256 rows x 128B
            int i = tid + j * 256;
            int row = i >> 3, cb = (i & 7) * 16;
            uint32_t so = SW128((uint32_t)(row * 128 + cb));
            cp16(st + OFF_A + so, (const char*)Af + ((size_t)(bm0 + row) * KDIM + k0) * 2 + cb);
        }
        #pragma unroll
        for (int j = 0; j < 4; j++) {              // B: 128 rows x 128B
            int i = tid + j * 256;
            int row = i >> 3, cb = (i & 7) * 16;
            uint32_t so = SW128((uint32_t)(row * 128 + cb));
            cp16(st + OFF_B + so, (const char*)Bf + ((size_t)(bn0 + row) * KDIM + k0) * 2 + cb);
        }
        asm volatile("cp.async.commit_group;\n");
    };

    load_chunk(0);
    load_chunk(1);

    const int NC = KDIM / 64;
    for (int c = 0; c < NC; c++) {
        if (c == NC - 1) asm volatile("cp.async.wait_group 0;\n");
        else             asm volatile("cp.async.wait_group 1;\n");
        __syncthreads();
        if (c + 2 < NC) load_chunk(c + 2);

        uint32_t st = sb + (uint32_t)(c % 3) * STAGE_BYTES;
        #pragma unroll
        for (int ks = 0; ks < 4; ks++) {
            uint32_t ah[4][4], bh[4][4];
            int lrow = (lane & 7) + ((lane >> 3) & 1) * 8;
            int lcb  = ks * 32 + (lane >> 4) * 16;
            #pragma unroll
            for (int mt = 0; mt < 4; mt++) {
                int arow = warp_m + mt * 16 + lrow;
                LDSM_X4(ah[mt], st + OFF_A + SW128((uint32_t)(arow * 128 + lcb)));
            }
            #pragma unroll
            for (int nt = 0; nt < 4; nt++) {
                int brow = warp_n + nt * 16 + lrow;
                LDSM_X4(bh[nt], st + OFF_B + SW128((uint32_t)(brow * 128 + lcb)));
            }
            #pragma unroll
            for (int mt = 0; mt < 4; mt++) {
                #pragma unroll
                for (int nt4 = 0; nt4 < 4; nt4++) {
                    MMA16816(acc[mt][2*nt4],   ah[mt], bh[nt4][0], bh[nt4][2]);
                    MMA16816(acc[mt][2*nt4+1], ah[mt], bh[nt4][1], bh[nt4][3]);
                }
            }
        }
    }

    const int rbase = bm0 + warp_m + (lane >> 2);
    const int cbase = bn0 + warp_n + (lane & 3) * 2;
    #pragma unroll
    for (int mt = 0; mt < 4; mt++) {
        #pragma unroll
        for (int hh = 0; hh < 2; hh++) {
            int row = rbase + mt * 16 + hh * 8;
            #pragma unroll
            for (int nt = 0; nt < 8; nt++) {
                int col = cbase + nt * 8;
                float2 v = make_float2(acc[mt][nt][2*hh], acc[mt][nt][2*hh+1]);
                if (MODE == 0) {
                    *(float2*)&C[(size_t)row * 2048 + col] = v;
                } else {
                    int b = row >> 11, tq = row & (T_SEQ - 1), d = col & 127;
                    if (col < 2048) {
                        int h = col >> 7;
                        *(float2*)(g_q + (((size_t)(b * N_HEADS + h) * T_SEQ + tq) * HD + d)) = v;
                    } else if (col < 2560) {
                        int h = (col - 2048) >> 7;
                        *(float2*)(g_k + (((size_t)(b * N_KV + h) * T_SEQ + tq) * HD + d)) = v;
                    } else {
                        int h = (col - 2560) >> 7;
                        size_t idx = ((size_t)(b * N_KV + h) * T_SEQ + tq) * HD + d;
                        *(uint32_t*)&g_vF[idx] = packh(v.x, v.y);
                    }
                }
            }
        }
    }
}

// ---------------- fused RoPE (q then k): fp32 in -> scaled fp16 out ----------------
#define QPAIRS ((long)B_SZ * N_HEADS * T_SEQ * 64)
#define KPAIRS ((long)B_SZ * N_KV   * T_SEQ * 64)

__global__ void rope_both(const float* __restrict__ qsrc, const float* __restrict__ ksrc,
                          __half* __restrict__ qdst, __half* __restrict__ kdst,
                          float qscale)
{
    long idx = (long)blockIdx.x * blockDim.x + threadIdx.x;
    if (idx >= QPAIRS + KPAIRS) return;
    const float* src; __half* dst; float scale;
    if (idx < QPAIRS) { src = qsrc; dst = qdst; scale = qscale; }
    else              { src = ksrc; dst = kdst; scale = 1.0f; idx -= QPAIRS; }
    int  i   = (int)(idx & 63);
    long row = idx >> 6;
    int  tpos = (int)(row & (T_SEQ - 1));
    const float* p = src + row * HD;
    float inv = __expf(-((float)i / 64.0f) * 13.815510557964274f);
    float s, c;
    sincosf((float)tpos * inv, &s, &c);
    float x1 = p[i], x2 = p[i + 64];
    dst[row * HD + i]      = __float2half_rn((x1 * c - x2 * s) * scale);
    dst[row * HD + i + 64] = __float2half_rn((x2 * c + x1 * s) * scale);
}

// ---------------- tensor-core flash attention (fp16, base-2 softmax) ----------
#define ATT_K 0
#define ATT_V 16384
#define ATT_STAGE 32768
#define ATT_SMEM (3 * ATT_STAGE)   // 98304

__device__ __forceinline__ uint32_t swz256(int row, int cb) {
    return (uint32_t)(row * 256 + ((cb ^ (row & 7)) << 4));
}

__global__ __launch_bounds__(256, 1)
void attn_mma(const __half* __restrict__ qf, const __half* __restrict__ kf,
              const __half* __restrict__ vf, __half* __restrict__ oF)
{
    extern __shared__ __align__(1024) char smem[];
    const uint32_t sb = smem_to_u32(smem);
    const int tid  = threadIdx.x;
    const int w    = tid >> 5;
    const int lane = tid & 31;
    const int qt   = (gridDim.x - 1) - blockIdx.x;
    const int bh   = blockIdx.y;
    const int b    = bh >> 4;
    const int h    = bh & 15;
    const int kvh  = h >> 2;

    const size_t qoff = ((size_t)bh * T_SEQ + (size_t)qt * 128) * HD;
    const size_t koff = (size_t)(b * N_KV + kvh) * T_SEQ * HD;

    const int r4 = lane >> 2;
    const int lrow = (lane & 7) + ((lane >> 3) & 1) * 8;

    // ---- preamble: stage Q in stage-0 region, pull to registers ----
    #pragma unroll
    for (int j = 0; j < 8; j++) {
        int i = tid + j * 256;
        int row = i >> 4, cb = i & 15;
        cp16(sb + swz256(row, cb), (const char*)qf + (qoff + (size_t)row * HD) * 2 + cb * 16);
    }
    asm volatile("cp.async.commit_group;\n");
    asm volatile("cp.async.wait_group 0;\n");
    __syncthreads();

    uint32_t qr[8][4];
    #pragma unroll
    for (int ks = 0; ks < 8; ks++) {
        int cb = 2 * ks + (lane >> 4);
        LDSM_X4(qr[ks], sb + swz256(16 * w + lrow, cb));
    }
    __syncthreads();

    auto load_stage = [&](int kt) {
        uint32_t st = sb + (uint32_t)(kt % 3) * ATT_STAGE;
        size_t base = (koff + (size_t)kt * 64 * HD) * 2;
        #pragma unroll
        for (int j = 0; j < 4; j++) {
            int i = tid + j * 256;
            int row = i >> 4, cb = i & 15;
            uint32_t so = swz256(row, cb);
            size_t go = base + (size_t)row * 256 + cb * 16;
            cp16(st + ATT_K + so, (const char*)kf + go);
            cp16(st + ATT_V + so, (const char*)vf + go);
        }
        asm volatile("cp.async.commit_group;\n");
    };

    const int nkt = 2 * (qt + 1);
    load_stage(0);
    load_stage(1);

    float acc[16][4];
    #pragma unroll
    for (int nt = 0; nt < 16; nt++)
        #pragma unroll
        for (int i = 0; i < 4; i++) acc[nt][i] = 0.f;
    float m0 = -1e30f, m1 = -1e30f, l0 = 0.f, l1 = 0.f;

    const int qrow0 = qt * 128 + 16 * w + r4;
    const int wmax  = qt * 128 + 16 * w + 15;

    for (int kt = 0; kt < nkt; kt++) {
        if (kt == nkt - 1) asm volatile("cp.async.wait_group 0;\n");
        else               asm volatile("cp.async.wait_group 1;\n");
        __syncthreads();
        if (kt + 2 < nkt) load_stage(kt + 2);

        int kvbase = kt * 64;
        if (kvbase > wmax) continue;
        uint32_t st = sb + (uint32_t)(kt % 3) * ATT_STAGE;

        // ---- S = Q K^T (log2e * scale pre-folded into q) ----
        float sacc[8][4];
        #pragma unroll
        for (int nt = 0; nt < 8; nt++)
            #pragma unroll
            for (int i = 0; i < 4; i++) sacc[nt][i] = 0.f;

        #pragma unroll
        for (int ks = 0; ks < 8; ks++) {
            #pragma unroll
            for (int nt2 = 0; nt2 < 4; nt2++) {
                int cb = 2 * ks + (lane >> 4);
                uint32_t k4[4];
                LDSM_X4(k4, st + ATT_K + swz256(16 * nt2 + lrow, cb));
                MMA16816(sacc[2*nt2],   qr[ks], k4[0], k4[2]);
                MMA16816(sacc[2*nt2+1], qr[ks], k4[1], k4[3]);
            }
        }

        // ---- causal mask ----
        if (kvbase + 63 > qrow0) {
            #pragma unroll
            for (int nt = 0; nt < 8; nt++) {
                int col = kvbase + 8 * nt + (lane & 3) * 2;
                if (col     > qrow0)     sacc[nt][0] = -1e30f;
                if (col + 1 > qrow0)     sacc[nt][1] = -1e30f;
                if (col     > qrow0 + 8) sacc[nt][2] = -1e30f;
                if (col + 1 > qrow0 + 8) sacc[nt][3] = -1e30f;
            }
        }

        // ---- online softmax (base 2) ----
        float ml0 = -1e30f, ml1 = -1e30f;
        #pragma unroll
        for (int nt = 0; nt < 8; nt++) {
            ml0 = fmaxf(ml0, fmaxf(sacc[nt][0], sacc[nt][1]));
            ml1 = fmaxf(ml1, fmaxf(sacc[nt][2], sacc[nt][3]));
        }
        ml0 = fmaxf(ml0, __shfl_xor_sync(0xffffffffu, ml0, 1));
        ml0 = fmaxf(ml0, __shfl_xor_sync(0xffffffffu, ml0, 2));
        ml1 = fmaxf(ml1, __shfl_xor_sync(0xffffffffu, ml1, 1));
        ml1 = fmaxf(ml1, __shfl_xor_sync(0xffffffffu, ml1, 2));
        float mn0 = fmaxf(m0, ml0), mn1 = fmaxf(m1, ml1);
        float c0 = exp2f(m0 - mn0), c1 = exp2f(m1 - mn1);
        float ps0 = 0.f, ps1 = 0.f;
        #pragma unroll
        for (int nt = 0; nt < 8; nt++) {
            sacc[nt][0] = exp2f(sacc[nt][0] - mn0);
            sacc[nt][1] = exp2f(sacc[nt][1] - mn0);
            sacc[nt][2] = exp2f(sacc[nt][2] - mn1);
            sacc[nt][3] = exp2f(sacc[nt][3] - mn1);
            ps0 += sacc[nt][0] + sacc[nt][1];
            ps1 += sacc[nt][2] + sacc[nt][3];
        }
        ps0 += __shfl_xor_sync(0xffffffffu, ps0, 1);
        ps0 += __shfl_xor_sync(0xffffffffu, ps0, 2);
        ps1 += __shfl_xor_sync(0xffffffffu, ps1, 1);
        ps1 += __shfl_xor_sync(0xffffffffu, ps1, 2);
        l0 = l0 * c0 + ps0;
        l1 = l1 * c1 + ps1;
        m0 = mn0; m1 = mn1;
        #pragma unroll
        for (int nt = 0; nt < 16; nt++) {
            acc[nt][0] *= c0; acc[nt][1] *= c0;
            acc[nt][2] *= c1; acc[nt][3] *= c1;
        }

        // ---- pack P fragments ----
        uint32_t ph[4][4];
        #pragma unroll
        for (int j = 0; j < 4; j++) {
            #pragma unroll
            for (int half = 0; half < 2; half++) {
                ph[j][2*half]   = packh(sacc[2*j+half][0], sacc[2*j+half][1]);
                ph[j][2*half+1] = packh(sacc[2*j+half][2], sacc[2*j+half][3]);
            }
        }

        // ---- O += P V ----
        #pragma unroll
        for (int j = 0; j < 4; j++) {
            #pragma unroll
            for (int dt = 0; dt < 8; dt++) {
                int cb = 2 * dt + (lane >> 4);
                uint32_t v4[4];
                LDSM_X4_T(v4, st + ATT_V + swz256(16 * j + lrow, cb));
                MMA16816(acc[2*dt],   ph[j], v4[0], v4[1]);
                MMA16816(acc[2*dt+1], ph[j], v4[2], v4[3]);
            }
        }
    }

    // ---- epilogue ----
    float i0 = 1.f / l0, i1 = 1.f / l1;
    const int trow0 = qt * 128 + 16 * w + r4;
    const size_t orow0 = (size_t)(b * T_SEQ + trow0) * 2048 + h * 128;
    const size_t orow1 = orow0 + 8 * 2048;
    #pragma unroll
    for (int nt = 0; nt < 16; nt++) {
        int d = 8 * nt + (lane & 3) * 2;
        *(uint32_t*)&oF[orow0 + d] = packh(acc[nt][0] * i0, acc[nt][1] * i0);
        *(uint32_t*)&oF[orow1 + d] = packh(acc[nt][2] * i1, acc[nt][3] * i1);
    }
}

// ---------------- launch ----------------
extern "C" void kernel_launch(void* const* d_in, const int* in_sizes, int n_in,
                              void* d_out, int out_size)
{
    const float* x   = (const float*)d_in[0];
    const float* w_q = (const float*)d_in[1];
    const float* w_k = (const float*)d_in[2];
    const float* w_v = (const float*)d_in[3];
    const float* w_o = (const float*)d_in[4];
    float* out = (float*)d_out;

    float *q, *k;
    __half *xF, *wF, *woF, *aF, *qF, *kF, *vF;
    cudaGetSymbolAddress((void**)&q,   g_q);
    cudaGetSymbolAddress((void**)&k,   g_k);
    cudaGetSymbolAddress((void**)&xF,  g_xF);
    cudaGetSymbolAddress((void**)&wF,  g_wF);
    cudaGetSymbolAddress((void**)&woF, g_woF);
    cudaGetSymbolAddress((void**)&aF,  g_aF);
    cudaGetSymbolAddress((void**)&qF,  g_qF);
    cudaGetSymbolAddress((void**)&kF,  g_kF);
    cudaGetSymbolAddress((void**)&vF,  g_vF);

    // fused input conversion
    convert_all<<<(CV_WO + 255) / 256, 256>>>(x, w_q, w_k, w_v, w_o, xF, wF, woF);

    cudaFuncSetAttribute(gemm_fp16<0>, cudaFuncAttributeMaxDynamicSharedMemorySize, GEMM_SMEM);
    cudaFuncSetAttribute(gemm_fp16<1>, cudaFuncAttributeMaxDynamicSharedMemorySize, GEMM_SMEM);

    // fused QKV projection (q,k fp32; v direct fp16)
    gemm_fp16<1><<<dim3(3072 / 128, MROWS / 256), 256, GEMM_SMEM>>>(xF, wF, q);

    // fused RoPE q+k -> fp16 (softmax scale * log2e folded into q)
    {
        long tp = QPAIRS + KPAIRS;
        rope_both<<<(unsigned)((tp + 255) / 256), 256>>>(q, k, qF, kF,
            0.08838834764831845f * 1.4426950408889634f);
    }

    // tensor-core attention -> g_aF
    cudaFuncSetAttribute(attn_mma, cudaFuncAttributeMaxDynamicSharedMemorySize, ATT_SMEM);
    attn_mma<<<dim3(T_SEQ / 128, B_SZ * N_HEADS), 256, ATT_SMEM>>>(qF, kF, vF, aF);

    // O projection
    gemm_fp16<0><<<dim3(2048 / 128, MROWS / 256), 256, GEMM_SMEM>>>(aF, woF, out);
}

// round 11
// speedup vs baseline: 2.6997x; 1.0553x over previous
#include <cuda_runtime.h>
#include <cuda_fp16.h>
#include <math.h>
#include <stdint.h>

#define B_SZ    2
#define T_SEQ   2048
#define D_MODEL 2048
#define N_HEADS 16
#define N_KV    4
#define HD      128
#define KDIM    2048
#define MROWS   (B_SZ * T_SEQ)          // 4096

// ---------------- scratch (static device globals; no allocs) ----------------
__device__ float g_q[(size_t)B_SZ * N_HEADS * T_SEQ * HD];
__device__ float g_k[(size_t)B_SZ * N_KV   * T_SEQ * HD];

__device__ __half g_xF[(size_t)MROWS * KDIM];
__device__ __half g_wF[(size_t)3072 * KDIM];    // wq|wk|wv stacked
__device__ __half g_woF[(size_t)2048 * KDIM];
__device__ __half g_aF[(size_t)MROWS * KDIM];

__device__ __half g_qF[(size_t)B_SZ * N_HEADS * T_SEQ * HD];
__device__ __half g_kF[(size_t)B_SZ * N_KV * T_SEQ * HD];
__device__ __half g_vF[(size_t)B_SZ * N_KV * T_SEQ * HD];

// ---------------- helpers ----------------
__device__ __forceinline__ uint32_t smem_to_u32(const void* p) {
    uint32_t a;
    asm("{ .reg .u64 t; cvta.to.shared.u64 t, %1; cvt.u32.u64 %0, t; }" : "=r"(a) : "l"(p));
    return a;
}
#define SW128(off) ((off) ^ (((off) >> 3) & 0x70))

__device__ __forceinline__ void cp16(uint32_t saddr, const void* g) {
    asm volatile("cp.async.cg.shared.global [%0], [%1], 16;\n" :: "r"(saddr), "l"(g));
}
#define LDSM_X4(r, a) \
    asm volatile("ldmatrix.sync.aligned.m8n8.x4.shared.b16 {%0,%1,%2,%3}, [%4];" \
        : "=r"((r)[0]), "=r"((r)[1]), "=r"((r)[2]), "=r"((r)[3]) : "r"(a))
#define LDSM_X4_T(r, a) \
    asm volatile("ldmatrix.sync.aligned.m8n8.x4.trans.shared.b16 {%0,%1,%2,%3}, [%4];" \
        : "=r"((r)[0]), "=r"((r)[1]), "=r"((r)[2]), "=r"((r)[3]) : "r"(a))
#define MMA16816(c, a, b0, b1) \
    asm volatile("mma.sync.aligned.m16n8k16.row.col.f32.f16.f16.f32 " \
        "{%0,%1,%2,%3}, {%4,%5,%6,%7}, {%8,%9}, {%0,%1,%2,%3};" \
        : "+f"((c)[0]), "+f"((c)[1]), "+f"((c)[2]), "+f"((c)[3]) \
        : "r"((a)[0]), "r"((a)[1]), "r"((a)[2]), "r"((a)[3]), "r"(b0), "r"(b1))

__device__ __forceinline__ uint32_t packh(float a, float b) {
    __half2 t = __floats2half2_rn(a, b);
    return reinterpret_cast<uint32_t&>(t);
}

// ---------------- fused fp32 -> fp16 conversion of all inputs ----------------
#define CV_X   2097152                       // float4 counts
#define CV_WQ  (CV_X  + 1048576)
#define CV_WK  (CV_WQ + 262144)
#define CV_WV  (CV_WK + 262144)
#define CV_WO  (CV_WV + 1048576)             // 4718592 total

__global__ void convert_all(const float* __restrict__ x,  const float* __restrict__ wq,
                            const float* __restrict__ wk, const float* __restrict__ wv,
                            const float* __restrict__ wo,
                            __half* __restrict__ xF, __half* __restrict__ wF,
                            __half* __restrict__ woF)
{
    int i = blockIdx.x * blockDim.x + threadIdx.x;
    if (i >= CV_WO) return;
    const float* src; __half* dst; int off;
    if      (i < CV_X)  { src = x;  dst = xF;  off = i; }
    else if (i < CV_WQ) { src = wq; dst = wF;  off = i - CV_X; }
    else if (i < CV_WK) { src = wk; dst = wF + (size_t)2048 * KDIM; off = i - CV_WQ; }
    else if (i < CV_WV) { src = wv; dst = wF + (size_t)2560 * KDIM; off = i - CV_WK; }
    else                { src = wo; dst = woF; off = i - CV_WV; }
    float4 v = ((const float4*)src)[off];
    ((__half2*)dst)[2 * off]     = __floats2half2_rn(v.x, v.y);
    ((__half2*)dst)[2 * off + 1] = __floats2half2_rn(v.z, v.w);
}

// ---------------- fp16 GEMM: C = A @ B^T, tile 128x128, 2 CTAs/SM ----------------
// 8 warps, each 32(M)x64(N). BK=64, 3-stage ring, 1 barrier per chunk.
// MODE 0: C row-major fp32. MODE 1: QKV scatter (q,k fp32; v fp16 direct).
#define OFF_A  0
#define OFF_B  16384
#define STAGE_BYTES 32768
#define GEMM_SMEM (3 * STAGE_BYTES)     // 98304

template<int MODE>
__global__ __launch_bounds__(256, 2)
void gemm_fp16(const __half* __restrict__ Af, const __half* __restrict__ Bf,
               float* __restrict__ C)
{
    extern __shared__ __align__(1024) char smem[];
    const uint32_t sb = smem_to_u32(smem);
    const int tid  = threadIdx.x;
    const int lane = tid & 31;
    const int wid  = tid >> 5;
    const int warp_m = (wid & 3) * 32;
    const int warp_n = (wid >> 2) * 64;
    const int bm0 = blockIdx.y * 128;
    const int bn0 = blockIdx.x * 128;

    float acc[2][8][4];
    #pragma unroll
    for (int mt = 0; mt < 2; mt++)
        #pragma unroll
        for (int nt = 0; nt < 8; nt++)
            #pragma unroll
            for (int i = 0; i < 4; i++) acc[mt][nt][i] = 0.f;

    auto load_chunk = [&](int c) {
        uint32_t st = sb + (uint32_t)(c % 3) * STAGE_BYTES;
        int k0 = c * 64;
        #pragma unroll
        for (int j = 0; j < 4; j++) {
            int i = tid + j * 256;
            int row = i >> 3, cb = (i & 7) * 16;
            uint32_t so = SW128((uint32_t)(row * 128 + cb));
            cp16(st + OFF_A + so, (const char*)Af + ((size_t)(bm0 + row) * KDIM + k0) * 2 + cb);
            cp16(st + OFF_B + so, (const char*)Bf + ((size_t)(bn0 + row) * KDIM + k0) * 2 + cb);
        }
        asm volatile("cp.async.commit_group;\n");
    };

    load_chunk(0);
    load_chunk(1);

    const int NC = KDIM / 64;
    for (int c = 0; c < NC; c++) {
        if (c == NC - 1) asm volatile("cp.async.wait_group 0;\n");
        else             asm volatile("cp.async.wait_group 1;\n");
        __syncthreads();
        if (c + 2 < NC) load_chunk(c + 2);

        uint32_t st = sb + (uint32_t)(c % 3) * STAGE_BYTES;
        #pragma unroll
        for (int ks = 0; ks < 4; ks++) {
            uint32_t ah[2][4], bh[4][4];
            int lrow = (lane & 7) + ((lane >> 3) & 1) * 8;
            int lcb  = ks * 32 + (lane >> 4) * 16;
            #pragma unroll
            for (int mt = 0; mt < 2; mt++) {
                int arow = warp_m + mt * 16 + lrow;
                LDSM_X4(ah[mt], st + OFF_A + SW128((uint32_t)(arow * 128 + lcb)));
            }
            #pragma unroll
            for (int nt = 0; nt < 4; nt++) {
                int brow = warp_n + nt * 16 + lrow;
                LDSM_X4(bh[nt], st + OFF_B + SW128((uint32_t)(brow * 128 + lcb)));
            }
            #pragma unroll
            for (int mt = 0; mt < 2; mt++) {
                #pragma unroll
                for (int nt4 = 0; nt4 < 4; nt4++) {
                    MMA16816(acc[mt][2*nt4],   ah[mt], bh[nt4][0], bh[nt4][2]);
                    MMA16816(acc[mt][2*nt4+1], ah[mt], bh[nt4][1], bh[nt4][3]);
                }
            }
        }
    }

    const int rbase = bm0 + warp_m + (lane >> 2);
    const int cbase = bn0 + warp_n + (lane & 3) * 2;
    #pragma unroll
    for (int mt = 0; mt < 2; mt++) {
        #pragma unroll
        for (int hh = 0; hh < 2; hh++) {
            int row = rbase + mt * 16 + hh * 8;
            #pragma unroll
            for (int nt = 0; nt < 8; nt++) {
                int col = cbase + nt * 8;
                float2 v = make_float2(acc[mt][nt][2*hh], acc[mt][nt][2*hh+1]);
                if (MODE == 0) {
                    *(float2*)&C[(size_t)row * 2048 + col] = v;
                } else {
                    int b = row >> 11, tq = row & (T_SEQ - 1), d = col & 127;
                    if (col < 2048) {
                        int h = col >> 7;
                        *(float2*)(g_q + (((size_t)(b * N_HEADS + h) * T_SEQ + tq) * HD + d)) = v;
                    } else if (col < 2560) {
                        int h = (col - 2048) >> 7;
                        *(float2*)(g_k + (((size_t)(b * N_KV + h) * T_SEQ + tq) * HD + d)) = v;
                    } else {
                        int h = (col - 2560) >> 7;
                        size_t idx = ((size_t)(b * N_KV + h) * T_SEQ + tq) * HD + d;
                        *(uint32_t*)&g_vF[idx] = packh(v.x, v.y);
                    }
                }
            }
        }
    }
}

// ---------------- fused RoPE (q then k): fp32 in -> scaled fp16 out ----------------
#define QPAIRS ((long)B_SZ * N_HEADS * T_SEQ * 64)
#define KPAIRS ((long)B_SZ * N_KV   * T_SEQ * 64)

__global__ void rope_both(const float* __restrict__ qsrc, const float* __restrict__ ksrc,
                          __half* __restrict__ qdst, __half* __restrict__ kdst,
                          float qscale)
{
    long idx = (long)blockIdx.x * blockDim.x + threadIdx.x;
    if (idx >= QPAIRS + KPAIRS) return;
    const float* src; __half* dst; float scale;
    if (idx < QPAIRS) { src = qsrc; dst = qdst; scale = qscale; }
    else              { src = ksrc; dst = kdst; scale = 1.0f; idx -= QPAIRS; }
    int  i   = (int)(idx & 63);
    long row = idx >> 6;
    int  tpos = (int)(row & (T_SEQ - 1));
    const float* p = src + row * HD;
    float inv = __expf(-((float)i / 64.0f) * 13.815510557964274f);
    float s, c;
    sincosf((float)tpos * inv, &s, &c);
    float x1 = p[i], x2 = p[i + 64];
    dst[row * HD + i]      = __float2half_rn((x1 * c - x2 * s) * scale);
    dst[row * HD + i + 64] = __float2half_rn((x2 * c + x1 * s) * scale);
}

// ---------------- tensor-core flash attention (fp16, base-2 softmax) ----------
#define ATT_K 0
#define ATT_V 16384
#define ATT_STAGE 32768
#define ATT_SMEM (3 * ATT_STAGE)   // 98304

__device__ __forceinline__ uint32_t swz256(int row, int cb) {
    return (uint32_t)(row * 256 + ((cb ^ (row & 7)) << 4));
}

__global__ __launch_bounds__(256, 1)
void attn_mma(const __half* __restrict__ qf, const __half* __restrict__ kf,
              const __half* __restrict__ vf, __half* __restrict__ oF)
{
    extern __shared__ __align__(1024) char smem[];
    const uint32_t sb = smem_to_u32(smem);
    const int tid  = threadIdx.x;
    const int w    = tid >> 5;
    const int lane = tid & 31;
    const int qt   = (gridDim.x - 1) - blockIdx.x;
    const int bh   = blockIdx.y;
    const int b    = bh >> 4;
    const int h    = bh & 15;
    const int kvh  = h >> 2;

    const size_t qoff = ((size_t)bh * T_SEQ + (size_t)qt * 128) * HD;
    const size_t koff = (size_t)(b * N_KV + kvh) * T_SEQ * HD;

    const int r4 = lane >> 2;
    const int lrow = (lane & 7) + ((lane >> 3) & 1) * 8;

    // ---- preamble: stage Q in stage-0 region, pull to registers ----
    #pragma unroll
    for (int j = 0; j < 8; j++) {
        int i = tid + j * 256;
        int row = i >> 4, cb = i & 15;
        cp16(sb + swz256(row, cb), (const char*)qf + (qoff + (size_t)row * HD) * 2 + cb * 16);
    }
    asm volatile("cp.async.commit_group;\n");
    asm volatile("cp.async.wait_group 0;\n");
    __syncthreads();

    uint32_t qr[8][4];
    #pragma unroll
    for (int ks = 0; ks < 8; ks++) {
        int cb = 2 * ks + (lane >> 4);
        LDSM_X4(qr[ks], sb + swz256(16 * w + lrow, cb));
    }
    __syncthreads();

    auto load_stage = [&](int kt) {
        uint32_t st = sb + (uint32_t)(kt % 3) * ATT_STAGE;
        size_t base = (koff + (size_t)kt * 64 * HD) * 2;
        #pragma unroll
        for (int j = 0; j < 4; j++) {
            int i = tid + j * 256;
            int row = i >> 4, cb = i & 15;
            uint32_t so = swz256(row, cb);
            size_t go = base + (size_t)row * 256 + cb * 16;
            cp16(st + ATT_K + so, (const char*)kf + go);
            cp16(st + ATT_V + so, (const char*)vf + go);
        }
        asm volatile("cp.async.commit_group;\n");
    };

    const int nkt = 2 * (qt + 1);
    load_stage(0);
    load_stage(1);

    float acc[16][4];
    #pragma unroll
    for (int nt = 0; nt < 16; nt++)
        #pragma unroll
        for (int i = 0; i < 4; i++) acc[nt][i] = 0.f;
    float m0 = -1e30f, m1 = -1e30f, l0 = 0.f, l1 = 0.f;

    const int qrow0 = qt * 128 + 16 * w + r4;
    const int wmax  = qt * 128 + 16 * w + 15;

    for (int kt = 0; kt < nkt; kt++) {
        if (kt == nkt - 1) asm volatile("cp.async.wait_group 0;\n");
        else               asm volatile("cp.async.wait_group 1;\n");
        __syncthreads();
        if (kt + 2 < nkt) load_stage(kt + 2);

        int kvbase = kt * 64;
        if (kvbase > wmax) continue;
        uint32_t st = sb + (uint32_t)(kt % 3) * ATT_STAGE;

        // ---- S = Q K^T (log2e * scale pre-folded into q) ----
        float sacc[8][4];
        #pragma unroll
        for (int nt = 0; nt < 8; nt++)
            #pragma unroll
            for (int i = 0; i < 4; i++) sacc[nt][i] = 0.f;

        #pragma unroll
        for (int ks = 0; ks < 8; ks++) {
            #pragma unroll
            for (int nt2 = 0; nt2 < 4; nt2++) {
                int cb = 2 * ks + (lane >> 4);
                uint32_t k4[4];
                LDSM_X4(k4, st + ATT_K + swz256(16 * nt2 + lrow, cb));
                MMA16816(sacc[2*nt2],   qr[ks], k4[0], k4[2]);
                MMA16816(sacc[2*nt2+1], qr[ks], k4[1], k4[3]);
            }
        }

        // ---- causal mask ----
        if (kvbase + 63 > qrow0) {
            #pragma unroll
            for (int nt = 0; nt < 8; nt++) {
                int col = kvbase + 8 * nt + (lane & 3) * 2;
                if (col     > qrow0)     sacc[nt][0] = -1e30f;
                if (col + 1 > qrow0)     sacc[nt][1] = -1e30f;
                if (col     > qrow0 + 8) sacc[nt][2] = -1e30f;
                if (col + 1 > qrow0 + 8) sacc[nt][3] = -1e30f;
            }
        }

        // ---- online softmax (base 2) ----
        float ml0 = -1e30f, ml1 = -1e30f;
        #pragma unroll
        for (int nt = 0; nt < 8; nt++) {
            ml0 = fmaxf(ml0, fmaxf(sacc[nt][0], sacc[nt][1]));
            ml1 = fmaxf(ml1, fmaxf(sacc[nt][2], sacc[nt][3]));
        }
        ml0 = fmaxf(ml0, __shfl_xor_sync(0xffffffffu, ml0, 1));
        ml0 = fmaxf(ml0, __shfl_xor_sync(0xffffffffu, ml0, 2));
        ml1 = fmaxf(ml1, __shfl_xor_sync(0xffffffffu, ml1, 1));
        ml1 = fmaxf(ml1, __shfl_xor_sync(0xffffffffu, ml1, 2));
        float mn0 = fmaxf(m0, ml0), mn1 = fmaxf(m1, ml1);
        float c0 = exp2f(m0 - mn0), c1 = exp2f(m1 - mn1);
        float ps0 = 0.f, ps1 = 0.f;
        #pragma unroll
        for (int nt = 0; nt < 8; nt++) {
            sacc[nt][0] = exp2f(sacc[nt][0] - mn0);
            sacc[nt][1] = exp2f(sacc[nt][1] - mn0);
            sacc[nt][2] = exp2f(sacc[nt][2] - mn1);
            sacc[nt][3] = exp2f(sacc[nt][3] - mn1);
            ps0 += sacc[nt][0] + sacc[nt][1];
            ps1 += sacc[nt][2] + sacc[nt][3];
        }
        ps0 += __shfl_xor_sync(0xffffffffu, ps0, 1);
        ps0 += __shfl_xor_sync(0xffffffffu, ps0, 2);
        ps1 += __shfl_xor_sync(0xffffffffu, ps1, 1);
        ps1 += __shfl_xor_sync(0xffffffffu, ps1, 2);
        l0 = l0 * c0 + ps0;
        l1 = l1 * c1 + ps1;
        m0 = mn0; m1 = mn1;
        #pragma unroll
        for (int nt = 0; nt < 16; nt++) {
            acc[nt][0] *= c0; acc[nt][1] *= c0;
            acc[nt][2] *= c1; acc[nt][3] *= c1;
        }

        // ---- pack P fragments ----
        uint32_t ph[4][4];
        #pragma unroll
        for (int j = 0; j < 4; j++) {
            #pragma unroll
            for (int half = 0; half < 2; half++) {
                ph[j][2*half]   = packh(sacc[2*j+half][0], sacc[2*j+half][1]);
                ph[j][2*half+1] = packh(sacc[2*j+half][2], sacc[2*j+half][3]);
            }
        }

        // ---- O += P V ----
        #pragma unroll
        for (int j = 0; j < 4; j++) {
            #pragma unroll
            for (int dt = 0; dt < 8; dt++) {
                int cb = 2 * dt + (lane >> 4);
                uint32_t v4[4];
                LDSM_X4_T(v4, st + ATT_V + swz256(16 * j + lrow, cb));
                MMA16816(acc[2*dt],   ph[j], v4[0], v4[1]);
                MMA16816(acc[2*dt+1], ph[j], v4[2], v4[3]);
            }
        }
    }

    // ---- epilogue ----
    float i0 = 1.f / l0, i1 = 1.f / l1;
    const int trow0 = qt * 128 + 16 * w + r4;
    const size_t orow0 = (size_t)(b * T_SEQ + trow0) * 2048 + h * 128;
    const size_t orow1 = orow0 + 8 * 2048;
    #pragma unroll
    for (int nt = 0; nt < 16; nt++) {
        int d = 8 * nt + (lane & 3) * 2;
        *(uint32_t*)&oF[orow0 + d] = packh(acc[nt][0] * i0, acc[nt][1] * i0);
        *(uint32_t*)&oF[orow1 + d] = packh(acc[nt][2] * i1, acc[nt][3] * i1);
    }
}

// ---------------- launch ----------------
extern "C" void kernel_launch(void* const* d_in, const int* in_sizes, int n_in,
                              void* d_out, int out_size)
{
    const float* x   = (const float*)d_in[0];
    const float* w_q = (const float*)d_in[1];
    const float* w_k = (const float*)d_in[2];
    const float* w_v = (const float*)d_in[3];
    const float* w_o = (const float*)d_in[4];
    float* out = (float*)d_out;

    float *q, *k;
    __half *xF, *wF, *woF, *aF, *qF, *kF, *vF;
    cudaGetSymbolAddress((void**)&q,   g_q);
    cudaGetSymbolAddress((void**)&k,   g_k);
    cudaGetSymbolAddress((void**)&xF,  g_xF);
    cudaGetSymbolAddress((void**)&wF,  g_wF);
    cudaGetSymbolAddress((void**)&woF, g_woF);
    cudaGetSymbolAddress((void**)&aF,  g_aF);
    cudaGetSymbolAddress((void**)&qF,  g_qF);
    cudaGetSymbolAddress((void**)&kF,  g_kF);
    cudaGetSymbolAddress((void**)&vF,  g_vF);

    // fused input conversion
    convert_all<<<(CV_WO + 255) / 256, 256>>>(x, w_q, w_k, w_v, w_o, xF, wF, woF);

    cudaFuncSetAttribute(gemm_fp16<0>, cudaFuncAttributeMaxDynamicSharedMemorySize, GEMM_SMEM);
    cudaFuncSetAttribute(gemm_fp16<1>, cudaFuncAttributeMaxDynamicSharedMemorySize, GEMM_SMEM);

    // fused QKV projection (q,k fp32; v direct fp16), 2 CTAs/SM
    gemm_fp16<1><<<dim3(3072 / 128, MROWS / 128), 256, GEMM_SMEM>>>(xF, wF, q);

    // fused RoPE q+k -> fp16 (softmax scale * log2e folded into q)
    {
        long tp = QPAIRS + KPAIRS;
        rope_both<<<(unsigned)((tp + 255) / 256), 256>>>(q, k, qF, kF,
            0.08838834764831845f * 1.4426950408889634f);
    }

    // tensor-core attention -> g_aF
    cudaFuncSetAttribute(attn_mma, cudaFuncAttributeMaxDynamicSharedMemorySize, ATT_SMEM);
    attn_mma<<<dim3(T_SEQ / 128, B_SZ * N_HEADS), 256, ATT_SMEM>>>(qF, kF, vF, aF);

    // O projection, 2 CTAs/SM
    gemm_fp16<0><<<dim3(2048 / 128, MROWS / 128), 256, GEMM_SMEM>>>(aF, woF, out);
}

// round 12
// speedup vs baseline: 2.7568x; 1.0212x over previous
#include <cuda_runtime.h>
#include <cuda_fp16.h>
#include <math.h>
#include <stdint.h>

#define B_SZ    2
#define T_SEQ   2048
#define D_MODEL 2048
#define N_HEADS 16
#define N_KV    4
#define HD      128
#define KDIM    2048
#define MROWS   (B_SZ * T_SEQ)          // 4096

// ---------------- scratch (static device globals; no allocs) ----------------
__device__ __half g_xF[(size_t)MROWS * KDIM];
__device__ __half g_wF[(size_t)3072 * KDIM];    // wq|wk|wv stacked
__device__ __half g_woF[(size_t)2048 * KDIM];
__device__ __half g_aF[(size_t)MROWS * KDIM];

__device__ __half g_qI[(size_t)B_SZ * N_HEADS * T_SEQ * HD];  // pre-RoPE q (fp16)
__device__ __half g_kI[(size_t)B_SZ * N_KV * T_SEQ * HD];     // pre-RoPE k (fp16)
__device__ __half g_qF[(size_t)B_SZ * N_HEADS * T_SEQ * HD];
__device__ __half g_kF[(size_t)B_SZ * N_KV * T_SEQ * HD];
__device__ __half g_vF[(size_t)B_SZ * N_KV * T_SEQ * HD];

// ---------------- helpers ----------------
__device__ __forceinline__ uint32_t smem_to_u32(const void* p) {
    uint32_t a;
    asm("{ .reg .u64 t; cvta.to.shared.u64 t, %1; cvt.u32.u64 %0, t; }" : "=r"(a) : "l"(p));
    return a;
}
#define SW128(off) ((off) ^ (((off) >> 3) & 0x70))

__device__ __forceinline__ void cp16(uint32_t saddr, const void* g) {
    asm volatile("cp.async.cg.shared.global [%0], [%1], 16;\n" :: "r"(saddr), "l"(g));
}
#define LDSM_X4(r, a) \
    asm volatile("ldmatrix.sync.aligned.m8n8.x4.shared.b16 {%0,%1,%2,%3}, [%4];" \
        : "=r"((r)[0]), "=r"((r)[1]), "=r"((r)[2]), "=r"((r)[3]) : "r"(a))
#define LDSM_X4_T(r, a) \
    asm volatile("ldmatrix.sync.aligned.m8n8.x4.trans.shared.b16 {%0,%1,%2,%3}, [%4];" \
        : "=r"((r)[0]), "=r"((r)[1]), "=r"((r)[2]), "=r"((r)[3]) : "r"(a))
#define MMA16816(c, a, b0, b1) \
    asm volatile("mma.sync.aligned.m16n8k16.row.col.f32.f16.f16.f32 " \
        "{%0,%1,%2,%3}, {%4,%5,%6,%7}, {%8,%9}, {%0,%1,%2,%3};" \
        : "+f"((c)[0]), "+f"((c)[1]), "+f"((c)[2]), "+f"((c)[3]) \
        : "r"((a)[0]), "r"((a)[1]), "r"((a)[2]), "r"((a)[3]), "r"(b0), "r"(b1))

__device__ __forceinline__ uint32_t packh(float a, float b) {
    __half2 t = __floats2half2_rn(a, b);
    return reinterpret_cast<uint32_t&>(t);
}

// ---------------- fused fp32 -> fp16 conversion of all inputs ----------------
#define CV_X   2097152                       // float4 counts
#define CV_WQ  (CV_X  + 1048576)
#define CV_WK  (CV_WQ + 262144)
#define CV_WV  (CV_WK + 262144)
#define CV_WO  (CV_WV + 1048576)             // 4718592 total

__global__ void convert_all(const float* __restrict__ x,  const float* __restrict__ wq,
                            const float* __restrict__ wk, const float* __restrict__ wv,
                            const float* __restrict__ wo,
                            __half* __restrict__ xF, __half* __restrict__ wF,
                            __half* __restrict__ woF)
{
    int i = blockIdx.x * blockDim.x + threadIdx.x;
    if (i >= CV_WO) return;
    const float* src; __half* dst; int off;
    if      (i < CV_X)  { src = x;  dst = xF;  off = i; }
    else if (i < CV_WQ) { src = wq; dst = wF;  off = i - CV_X; }
    else if (i < CV_WK) { src = wk; dst = wF + (size_t)2048 * KDIM; off = i - CV_WQ; }
    else if (i < CV_WV) { src = wv; dst = wF + (size_t)2560 * KDIM; off = i - CV_WK; }
    else                { src = wo; dst = woF; off = i - CV_WV; }
    float4 v = ((const float4*)src)[off];
    ((__half2*)dst)[2 * off]     = __floats2half2_rn(v.x, v.y);
    ((__half2*)dst)[2 * off + 1] = __floats2half2_rn(v.z, v.w);
}

// ---------------- fp16 GEMM: C = A @ B^T, tile 128x128, 2 CTAs/SM ----------------
// MODE 0: C row-major fp32. MODE 1: QKV scatter — q,k,v all fp16 direct.
#define OFF_A  0
#define OFF_B  16384
#define STAGE_BYTES 32768
#define GEMM_SMEM (3 * STAGE_BYTES)     // 98304

template<int MODE>
__global__ __launch_bounds__(256, 2)
void gemm_fp16(const __half* __restrict__ Af, const __half* __restrict__ Bf,
               float* __restrict__ C)
{
    extern __shared__ __align__(1024) char smem[];
    const uint32_t sb = smem_to_u32(smem);
    const int tid  = threadIdx.x;
    const int lane = tid & 31;
    const int wid  = tid >> 5;
    const int warp_m = (wid & 3) * 32;
    const int warp_n = (wid >> 2) * 64;
    const int bm0 = blockIdx.y * 128;
    const int bn0 = blockIdx.x * 128;

    float acc[2][8][4];
    #pragma unroll
    for (int mt = 0; mt < 2; mt++)
        #pragma unroll
        for (int nt = 0; nt < 8; nt++)
            #pragma unroll
            for (int i = 0; i < 4; i++) acc[mt][nt][i] = 0.f;

    auto load_chunk = [&](int c) {
        uint32_t st = sb + (uint32_t)(c % 3) * STAGE_BYTES;
        int k0 = c * 64;
        #pragma unroll
        for (int j = 0; j < 4; j++) {
            int i = tid + j * 256;
            int row = i >> 3, cb = (i & 7) * 16;
            uint32_t so = SW128((uint32_t)(row * 128 + cb));
            cp16(st + OFF_A + so, (const char*)Af + ((size_t)(bm0 + row) * KDIM + k0) * 2 + cb);
            cp16(st + OFF_B + so, (const char*)Bf + ((size_t)(bn0 + row) * KDIM + k0) * 2 + cb);
        }
        asm volatile("cp.async.commit_group;\n");
    };

    load_chunk(0);
    load_chunk(1);

    const int NC = KDIM / 64;
    for (int c = 0; c < NC; c++) {
        if (c == NC - 1) asm volatile("cp.async.wait_group 0;\n");
        else             asm volatile("cp.async.wait_group 1;\n");
        __syncthreads();
        if (c + 2 < NC) load_chunk(c + 2);

        uint32_t st = sb + (uint32_t)(c % 3) * STAGE_BYTES;
        #pragma unroll
        for (int ks = 0; ks < 4; ks++) {
            uint32_t ah[2][4], bh[4][4];
            int lrow = (lane & 7) + ((lane >> 3) & 1) * 8;
            int lcb  = ks * 32 + (lane >> 4) * 16;
            #pragma unroll
            for (int mt = 0; mt < 2; mt++) {
                int arow = warp_m + mt * 16 + lrow;
                LDSM_X4(ah[mt], st + OFF_A + SW128((uint32_t)(arow * 128 + lcb)));
            }
            #pragma unroll
            for (int nt = 0; nt < 4; nt++) {
                int brow = warp_n + nt * 16 + lrow;
                LDSM_X4(bh[nt], st + OFF_B + SW128((uint32_t)(brow * 128 + lcb)));
            }
            #pragma unroll
            for (int mt = 0; mt < 2; mt++) {
                #pragma unroll
                for (int nt4 = 0; nt4 < 4; nt4++) {
                    MMA16816(acc[mt][2*nt4],   ah[mt], bh[nt4][0], bh[nt4][2]);
                    MMA16816(acc[mt][2*nt4+1], ah[mt], bh[nt4][1], bh[nt4][3]);
                }
            }
        }
    }

    const int rbase = bm0 + warp_m + (lane >> 2);
    const int cbase = bn0 + warp_n + (lane & 3) * 2;
    #pragma unroll
    for (int mt = 0; mt < 2; mt++) {
        #pragma unroll
        for (int hh = 0; hh < 2; hh++) {
            int row = rbase + mt * 16 + hh * 8;
            #pragma unroll
            for (int nt = 0; nt < 8; nt++) {
                int col = cbase + nt * 8;
                float2 v = make_float2(acc[mt][nt][2*hh], acc[mt][nt][2*hh+1]);
                if (MODE == 0) {
                    *(float2*)&C[(size_t)row * 2048 + col] = v;
                } else {
                    int b = row >> 11, tq = row & (T_SEQ - 1), d = col & 127;
                    __half* base;
                    if (col < 2048) {
                        int h = col >> 7;
                        base = g_qI + (((size_t)(b * N_HEADS + h) * T_SEQ + tq) * HD + d);
                    } else if (col < 2560) {
                        int h = (col - 2048) >> 7;
                        base = g_kI + (((size_t)(b * N_KV + h) * T_SEQ + tq) * HD + d);
                    } else {
                        int h = (col - 2560) >> 7;
                        base = g_vF + (((size_t)(b * N_KV + h) * T_SEQ + tq) * HD + d);
                    }
                    *(uint32_t*)base = packh(v.x, v.y);
                }
            }
        }
    }
}

// ---------------- fused RoPE (q then k): fp16 in -> scaled fp16 out ----------------
#define QPAIRS ((long)B_SZ * N_HEADS * T_SEQ * 64)
#define KPAIRS ((long)B_SZ * N_KV   * T_SEQ * 64)

__global__ void rope_both(const __half* __restrict__ qsrc, const __half* __restrict__ ksrc,
                          __half* __restrict__ qdst, __half* __restrict__ kdst,
                          float qscale)
{
    long idx = (long)blockIdx.x * blockDim.x + threadIdx.x;
    if (idx >= QPAIRS + KPAIRS) return;
    const __half* src; __half* dst; float scale;
    if (idx < QPAIRS) { src = qsrc; dst = qdst; scale = qscale; }
    else              { src = ksrc; dst = kdst; scale = 1.0f; idx -= QPAIRS; }
    int  i   = (int)(idx & 63);
    long row = idx >> 6;
    int  tpos = (int)(row & (T_SEQ - 1));
    const __half* p = src + row * HD;
    float inv = __expf(-((float)i / 64.0f) * 13.815510557964274f);
    float s, c;
    sincosf((float)tpos * inv, &s, &c);
    float x1 = __half2float(p[i]), x2 = __half2float(p[i + 64]);
    dst[row * HD + i]      = __float2half_rn((x1 * c - x2 * s) * scale);
    dst[row * HD + i + 64] = __float2half_rn((x2 * c + x1 * s) * scale);
}

// ---------------- tensor-core flash attention (fp16, BN=128, base-2 softmax) ------
// BM=128 q-rows, 8 warps x 16 rows. Q persistent in smem; K+V 3-stage 64KB ring.
#define ATT_Q 0
#define ATT_ST0 32768
#define ATT_STAGE 65536
#define ATT_K 0
#define ATT_V 32768
#define ATT_SMEM (ATT_ST0 + 3 * ATT_STAGE)   // 229376

__device__ __forceinline__ uint32_t swz256(int row, int cb) {
    return (uint32_t)(row * 256 + ((cb ^ (row & 7)) << 4));
}

__global__ __launch_bounds__(256, 1)
void attn_mma(const __half* __restrict__ qf, const __half* __restrict__ kf,
              const __half* __restrict__ vf, __half* __restrict__ oF)
{
    extern __shared__ __align__(1024) char smem[];
    const uint32_t sb = smem_to_u32(smem);
    const int tid  = threadIdx.x;
    const int w    = tid >> 5;
    const int lane = tid & 31;
    const int qt   = (gridDim.x - 1) - blockIdx.x;
    const int bh   = blockIdx.y;
    const int b    = bh >> 4;
    const int h    = bh & 15;
    const int kvh  = h >> 2;

    const size_t qoff = ((size_t)bh * T_SEQ + (size_t)qt * 128) * HD;
    const size_t koff = (size_t)(b * N_KV + kvh) * T_SEQ * HD;

    const int r4 = lane >> 2;
    const int lrow = (lane & 7) + ((lane >> 3) & 1) * 8;

    // ---- Q tile into persistent smem (group 0) ----
    #pragma unroll
    for (int j = 0; j < 8; j++) {
        int i = tid + j * 256;
        int row = i >> 4, cb = i & 15;
        cp16(sb + ATT_Q + swz256(row, cb),
             (const char*)qf + (qoff + (size_t)row * HD) * 2 + cb * 16);
    }
    asm volatile("cp.async.commit_group;\n");

    auto load_stage = [&](int kt) {
        uint32_t st = sb + ATT_ST0 + (uint32_t)(kt % 3) * ATT_STAGE;
        size_t base = (koff + (size_t)kt * 128 * HD) * 2;
        #pragma unroll
        for (int j = 0; j < 8; j++) {
            int i = tid + j * 256;
            int row = i >> 4, cb = i & 15;
            uint32_t so = swz256(row, cb);
            size_t go = base + (size_t)row * 256 + cb * 16;
            cp16(st + ATT_K + so, (const char*)kf + go);
            cp16(st + ATT_V + so, (const char*)vf + go);
        }
        asm volatile("cp.async.commit_group;\n");
    };

    const int nkt = qt + 1;
    load_stage(0);
    if (nkt > 1) load_stage(1);

    float acc[16][4];
    #pragma unroll
    for (int nt = 0; nt < 16; nt++)
        #pragma unroll
        for (int i = 0; i < 4; i++) acc[nt][i] = 0.f;
    float m0 = -1e30f, m1 = -1e30f, l0 = 0.f, l1 = 0.f;

    const int qrow0 = qt * 128 + 16 * w + r4;

    for (int kt = 0; kt < nkt; kt++) {
        if (kt == nkt - 1) asm volatile("cp.async.wait_group 0;\n");
        else               asm volatile("cp.async.wait_group 1;\n");
        __syncthreads();
        if (kt + 2 < nkt) load_stage(kt + 2);

        int kvbase = kt * 128;
        uint32_t st = sb + ATT_ST0 + (uint32_t)(kt % 3) * ATT_STAGE;

        // ---- S = Q K^T (log2e * scale pre-folded into q) ----
        float sacc[16][4];
        #pragma unroll
        for (int nt = 0; nt < 16; nt++)
            #pragma unroll
            for (int i = 0; i < 4; i++) sacc[nt][i] = 0.f;

        #pragma unroll
        for (int ks = 0; ks < 8; ks++) {
            int cb = 2 * ks + (lane >> 4);
            uint32_t q4[4];
            LDSM_X4(q4, sb + ATT_Q + swz256(16 * w + lrow, cb));
            #pragma unroll
            for (int nt2 = 0; nt2 < 8; nt2++) {
                uint32_t k4[4];
                LDSM_X4(k4, st + ATT_K + swz256(16 * nt2 + lrow, cb));
                MMA16816(sacc[2*nt2],   q4, k4[0], k4[2]);
                MMA16816(sacc[2*nt2+1], q4, k4[1], k4[3]);
            }
        }

        // ---- causal mask ----
        if (kvbase + 127 > qrow0) {
            #pragma unroll
            for (int nt = 0; nt < 16; nt++) {
                int col = kvbase + 8 * nt + (lane & 3) * 2;
                if (col     > qrow0)     sacc[nt][0] = -1e30f;
                if (col + 1 > qrow0)     sacc[nt][1] = -1e30f;
                if (col     > qrow0 + 8) sacc[nt][2] = -1e30f;
                if (col + 1 > qrow0 + 8) sacc[nt][3] = -1e30f;
            }
        }

        // ---- online softmax (base 2) ----
        float ml0 = -1e30f, ml1 = -1e30f;
        #pragma unroll
        for (int nt = 0; nt < 16; nt++) {
            ml0 = fmaxf(ml0, fmaxf(sacc[nt][0], sacc[nt][1]));
            ml1 = fmaxf(ml1, fmaxf(sacc[nt][2], sacc[nt][3]));
        }
        ml0 = fmaxf(ml0, __shfl_xor_sync(0xffffffffu, ml0, 1));
        ml0 = fmaxf(ml0, __shfl_xor_sync(0xffffffffu, ml0, 2));
        ml1 = fmaxf(ml1, __shfl_xor_sync(0xffffffffu, ml1, 1));
        ml1 = fmaxf(ml1, __shfl_xor_sync(0xffffffffu, ml1, 2));
        float mn0 = fmaxf(m0, ml0), mn1 = fmaxf(m1, ml1);
        float c0 = exp2f(m0 - mn0), c1 = exp2f(m1 - mn1);
        float ps0 = 0.f, ps1 = 0.f;
        #pragma unroll
        for (int nt = 0; nt < 16; nt++) {
            sacc[nt][0] = exp2f(sacc[nt][0] - mn0);
            sacc[nt][1] = exp2f(sacc[nt][1] - mn0);
            sacc[nt][2] = exp2f(sacc[nt][2] - mn1);
            sacc[nt][3] = exp2f(sacc[nt][3] - mn1);
            ps0 += sacc[nt][0] + sacc[nt][1];
            ps1 += sacc[nt][2] + sacc[nt][3];
        }
        ps0 += __shfl_xor_sync(0xffffffffu, ps0, 1);
        ps0 += __shfl_xor_sync(0xffffffffu, ps0, 2);
        ps1 += __shfl_xor_sync(0xffffffffu, ps1, 1);
        ps1 += __shfl_xor_sync(0xffffffffu, ps1, 2);
        l0 = l0 * c0 + ps0;
        l1 = l1 * c1 + ps1;
        m0 = mn0; m1 = mn1;
        #pragma unroll
        for (int nt = 0; nt < 16; nt++) {
            acc[nt][0] *= c0; acc[nt][1] *= c0;
            acc[nt][2] *= c1; acc[nt][3] *= c1;
        }

        // ---- pack P fragments ----
        uint32_t ph[8][4];
        #pragma unroll
        for (int j = 0; j < 8; j++) {
            #pragma unroll
            for (int half = 0; half < 2; half++) {
                ph[j][2*half]   = packh(sacc[2*j+half][0], sacc[2*j+half][1]);
                ph[j][2*half+1] = packh(sacc[2*j+half][2], sacc[2*j+half][3]);
            }
        }

        // ---- O += P V ----
        #pragma unroll
        for (int j = 0; j < 8; j++) {
            #pragma unroll
            for (int dt = 0; dt < 8; dt++) {
                int cb = 2 * dt + (lane >> 4);
                uint32_t v4[4];
                LDSM_X4_T(v4, st + ATT_V + swz256(16 * j + lrow, cb));
                MMA16816(acc[2*dt],   ph[j], v4[0], v4[1]);
                MMA16816(acc[2*dt+1], ph[j], v4[2], v4[3]);
            }
        }
    }

    // ---- epilogue ----
    float i0 = 1.f / l0, i1 = 1.f / l1;
    const int trow0 = qt * 128 + 16 * w + r4;
    const size_t orow0 = (size_t)(b * T_SEQ + trow0) * 2048 + h * 128;
    const size_t orow1 = orow0 + 8 * 2048;
    #pragma unroll
    for (int nt = 0; nt < 16; nt++) {
        int d = 8 * nt + (lane & 3) * 2;
        *(uint32_t*)&oF[orow0 + d] = packh(acc[nt][0] * i0, acc[nt][1] * i0);
        *(uint32_t*)&oF[orow1 + d] = packh(acc[nt][2] * i1, acc[nt][3] * i1);
    }
}

// ---------------- launch ----------------
extern "C" void kernel_launch(void* const* d_in, const int* in_sizes, int n_in,
                              void* d_out, int out_size)
{
    const float* x   = (const float*)d_in[0];
    const float* w_q = (const float*)d_in[1];
    const float* w_k = (const float*)d_in[2];
    const float* w_v = (const float*)d_in[3];
    const float* w_o = (const float*)d_in[4];
    float* out = (float*)d_out;

    __half *xF, *wF, *woF, *aF, *qI, *kI, *qF, *kF, *vF;
    cudaGetSymbolAddress((void**)&xF,  g_xF);
    cudaGetSymbolAddress((void**)&wF,  g_wF);
    cudaGetSymbolAddress((void**)&woF, g_woF);
    cudaGetSymbolAddress((void**)&aF,  g_aF);
    cudaGetSymbolAddress((void**)&qI,  g_qI);
    cudaGetSymbolAddress((void**)&kI,  g_kI);
    cudaGetSymbolAddress((void**)&qF,  g_qF);
    cudaGetSymbolAddress((void**)&kF,  g_kF);
    cudaGetSymbolAddress((void**)&vF,  g_vF);

    // fused input conversion
    convert_all<<<(CV_WO + 255) / 256, 256>>>(x, w_q, w_k, w_v, w_o, xF, wF, woF);

    cudaFuncSetAttribute(gemm_fp16<0>, cudaFuncAttributeMaxDynamicSharedMemorySize, GEMM_SMEM);
    cudaFuncSetAttribute(gemm_fp16<1>, cudaFuncAttributeMaxDynamicSharedMemorySize, GEMM_SMEM);

    // fused QKV projection (q,k,v all fp16 direct), 2 CTAs/SM
    gemm_fp16<1><<<dim3(3072 / 128, MROWS / 128), 256, GEMM_SMEM>>>(xF, wF, nullptr);

    // fused RoPE q+k (fp16 -> fp16, softmax scale * log2e folded into q)
    {
        long tp = QPAIRS + KPAIRS;
        rope_both<<<(unsigned)((tp + 255) / 256), 256>>>(qI, kI, qF, kF,
            0.08838834764831845f * 1.4426950408889634f);
    }

    // tensor-core attention (BN=128) -> g_aF
    cudaFuncSetAttribute(attn_mma, cudaFuncAttributeMaxDynamicSharedMemorySize, ATT_SMEM);
    attn_mma<<<dim3(T_SEQ / 128, B_SZ * N_HEADS), 256, ATT_SMEM>>>(qF, kF, vF, aF);

    // O projection, 2 CTAs/SM
    gemm_fp16<0><<<dim3(2048 / 128, MROWS / 128), 256, GEMM_SMEM>>>(aF, woF, out);
}